// round 13
// baseline (speedup 1.0000x reference)
#include <cuda_runtime.h>
#include <cuda_bf16.h>
#include <cstdint>

// ---------------------------------------------------------------------------
// InteractionGNN on GB300 — round 13: R10 base (best) + task-parallel fusion:
// per iteration, node work splits into node_q (Qa/Qb, critical path) and
// node_nn (h-update) fused into the edge launch's grid (overlapped).
// GEMM core: mma.sync bf16 3-term split (Ah*Wh + Ah*Wl + Al*Wh), fp32 accum.
// ---------------------------------------------------------------------------

#define N_NODES 100000
#define N_EDGES 600000
#define DD      128
#define NUM_ITERS 4

// ---------------- device scratch -------------------------------------------
__device__ float g_h  [(size_t)N_NODES * DD];
__device__ float g_h2 [(size_t)N_NODES * DD];
__device__ float g_m0 [(size_t)N_NODES * DD];
__device__ float g_m1 [(size_t)N_NODES * DD];
__device__ float g_e  [(size_t)N_EDGES * DD];
__device__ float g_pa [(size_t)N_NODES * DD];
__device__ float g_pb [(size_t)N_NODES * DD];
__device__ float g_pc [(size_t)N_NODES * DD];
__device__ float g_pd [(size_t)N_NODES * DD];
__device__ int   g_start[N_EDGES];
__device__ int   g_end  [N_EDGES];
// prepacked weights: 15 chunks x [128 n][128 k] bf16, hi and lo images
__device__ __nv_bfloat16 g_pwh[15 * 16384];
__device__ __nv_bfloat16 g_pwl[15 * 16384];

// ---------------- smem layout ------------------------------------------------
static constexpr int ROW_B  = 272;
static constexpr int SM_B1  = 64;     // 128 f32
static constexpr int SM_W2V = 576;    // 128 f32
static constexpr int SM_B2  = 1088;   // 128 f32
static constexpr int SM_B1P = 1600;   // 128 f32 (pe_b1 in fused kernel)
static constexpr int SM_IA  = 2112;   // 64 ints
static constexpr int SM_IB  = 2368;   // 64 ints
static constexpr int SM_AH  = 2688;
static constexpr int TBUF   = 64 * ROW_B;          // 17408
static constexpr int SM_AL  = SM_AH + TBUF;        // 20096
static constexpr int SM_BH  = SM_AL + TBUF;        // 37504
static constexpr int SM_BL  = SM_BH + TBUF;        // 54912
static constexpr int SM_TOTAL = SM_BL + TBUF;      // 72320
static constexpr int SM_STG = SM_AH;               // scatter staging overlay

static constexpr int EBLK = N_EDGES / 64;          // 9375
static constexpr int NBLK = (N_NODES + 63) / 64;   // 1563

// ---------------- helpers -----------------------------------------------------
__device__ __forceinline__ uint32_t smem_u32(const void* p) {
    uint32_t a;
    asm("{ .reg .u64 t; cvta.to.shared.u64 t, %1; cvt.u32.u64 %0, t; }"
        : "=r"(a) : "l"(p));
    return a;
}

#define LDSM_X4(R0, R1, R2, R3, ADDR) \
    asm volatile("ldmatrix.sync.aligned.m8n8.x4.shared.b16 {%0,%1,%2,%3}, [%4];" \
                 : "=r"(R0), "=r"(R1), "=r"(R2), "=r"(R3) : "r"(ADDR))

__device__ __forceinline__ void mma16816(float* c, const uint32_t* a,
                                         const uint32_t* b) {
    asm volatile(
        "mma.sync.aligned.m16n8k16.row.col.f32.bf16.bf16.f32 "
        "{%0,%1,%2,%3}, {%4,%5,%6,%7}, {%8,%9}, {%0,%1,%2,%3};"
        : "+f"(c[0]), "+f"(c[1]), "+f"(c[2]), "+f"(c[3])
        : "r"(a[0]), "r"(a[1]), "r"(a[2]), "r"(a[3]), "r"(b[0]), "r"(b[1]));
}

__device__ __forceinline__ uint32_t pack_bf2(float a, float b) {
    __nv_bfloat162 t = __floats2bfloat162_rn(a, b);
    return *reinterpret_cast<uint32_t*>(&t);
}

__device__ __forceinline__ void split2(float x, float y, uint32_t& H, uint32_t& L) {
    __nv_bfloat16 hx = __float2bfloat16(x);
    __nv_bfloat16 hy = __float2bfloat16(y);
    float lx = x - __bfloat162float(hx);
    float ly = y - __bfloat162float(hy);
    H = pack_bf2(__bfloat162float(hx), __bfloat162float(hy));
    L = pack_bf2(lx, ly);
}

#define CP_WAIT_ALL() asm volatile("cp.async.wait_group 0;" ::: "memory")

__device__ __forceinline__ void copyw_half(uint32_t sb, int tid, int chunk,
                                           int half) {
    const char* srcH = (const char*)(g_pwh + (size_t)chunk * 16384 + half * 8192);
    const char* srcL = (const char*)(g_pwl + (size_t)chunk * 16384 + half * 8192);
    #pragma unroll
    for (int i = tid; i < 1024; i += 256) {
        int rr = i >> 4, q = i & 15;
        uint32_t d = sb + SM_BH + rr * ROW_B + q * 16;
        asm volatile("cp.async.cg.shared.global [%0], [%1], 16;"
                     :: "r"(d), "l"(srcH + i * 16));
        asm volatile("cp.async.cg.shared.global [%0], [%1], 16;"
                     :: "r"(d + (uint32_t)TBUF), "l"(srcL + i * 16));
    }
    asm volatile("cp.async.commit_group;" ::: "memory");
}

template <int KSTEPS>
__device__ __forceinline__ void gemm3h(uint32_t sb, int m0, int nloc,
                                       int a_ro, int a_co, int b_ro, int b_co,
                                       float accp[4][4]) {
    #pragma unroll
    for (int ks = 0; ks < KSTEPS; ++ks) {
        const int k0 = ks * 16;
        uint32_t ah[4], al[4];
        {
            uint32_t ro = (uint32_t)(m0 + a_ro) * ROW_B + (uint32_t)(k0 + a_co) * 2;
            LDSM_X4(ah[0], ah[1], ah[2], ah[3], sb + SM_AH + ro);
            LDSM_X4(al[0], al[1], al[2], al[3], sb + SM_AL + ro);
        }
        uint32_t bh[4][2], bl[4][2];
        #pragma unroll
        for (int nb = 0; nb < 2; ++nb) {
            uint32_t ro = (uint32_t)(nloc + nb * 16 + b_ro) * ROW_B +
                          (uint32_t)(k0 + b_co) * 2;
            uint32_t r0, r1, r2, r3;
            LDSM_X4(r0, r1, r2, r3, sb + SM_BH + ro);
            bh[nb * 2][0] = r0; bh[nb * 2][1] = r1;
            bh[nb * 2 + 1][0] = r2; bh[nb * 2 + 1][1] = r3;
            LDSM_X4(r0, r1, r2, r3, sb + SM_BL + ro);
            bl[nb * 2][0] = r0; bl[nb * 2][1] = r1;
            bl[nb * 2 + 1][0] = r2; bl[nb * 2 + 1][1] = r3;
        }
        #pragma unroll
        for (int na = 0; na < 4; ++na) {
            mma16816(accp[na], ah, bh[na]);
            mma16816(accp[na], ah, bl[na]);
            mma16816(accp[na], al, bh[na]);
        }
    }
}

template <int KS>
__device__ __forceinline__ void layer_gemm_issued(uint32_t sb, int tid, int chunk,
                                                  int m0, int nloc,
                                                  int a_ro, int a_co,
                                                  int b_ro, int b_co,
                                                  float acc[2][4][4]) {
    CP_WAIT_ALL();
    __syncthreads();
    gemm3h<KS>(sb, m0, nloc, a_ro, a_co, b_ro, b_co, acc[0]);
    __syncthreads();
    copyw_half(sb, tid, chunk, 1);
    CP_WAIT_ALL();
    __syncthreads();
    gemm3h<KS>(sb, m0, nloc, a_ro, a_co, b_ro, b_co, acc[1]);
}

__device__ __forceinline__ void zacc2(float acc[2][4][4]) {
    #pragma unroll
    for (int q = 0; q < 32; ++q) (&acc[0][0][0])[q] = 0.f;
}

template <int SRC_K>
__device__ __forceinline__ void stage_a(char* smem, int wid, int lane, int row0,
                                        const float* __restrict__ src, int nrows) {
    for (int r = wid; r < 64; r += 8) {
        int grow = row0 + r;
        float4 v = make_float4(0.f, 0.f, 0.f, 0.f);
        if (grow < nrows && lane < SRC_K / 4)
            v = ((const float4*)(src + (size_t)grow * SRC_K))[lane];
        if (lane < SRC_K / 4) {
            uint32_t h0, l0, h1, l1;
            split2(v.x, v.y, h0, l0);
            split2(v.z, v.w, h1, l1);
            uint32_t off = r * ROW_B + lane * 8;
            *(uint2*)(smem + SM_AH + off) = make_uint2(h0, h1);
            *(uint2*)(smem + SM_AL + off) = make_uint2(l0, l1);
        }
    }
}

__device__ __forceinline__ void acc_to_A(char* smem, float acc[2][4][4],
                                         int m0, int nwn, int g, int tig,
                                         const float* b1s, bool relu) {
    const int rl = m0 + g;
    #pragma unroll
    for (int p = 0; p < 2; ++p)
        #pragma unroll
        for (int na = 0; na < 4; ++na) {
            int cc = p * 64 + nwn + na * 8 + 2 * tig;
            float bx = b1s ? b1s[cc] : 0.f;
            float by = b1s ? b1s[cc + 1] : 0.f;
            float v0 = acc[p][na][0] + bx, v1 = acc[p][na][1] + by;
            float v2 = acc[p][na][2] + bx, v3 = acc[p][na][3] + by;
            if (relu) {
                v0 = fmaxf(v0, 0.f); v1 = fmaxf(v1, 0.f);
                v2 = fmaxf(v2, 0.f); v3 = fmaxf(v3, 0.f);
            }
            uint32_t H, L;
            split2(v0, v1, H, L);
            *(uint32_t*)(smem + SM_AH + rl * ROW_B + cc * 2) = H;
            *(uint32_t*)(smem + SM_AL + rl * ROW_B + cc * 2) = L;
            split2(v2, v3, H, L);
            *(uint32_t*)(smem + SM_AH + (rl + 8) * ROW_B + cc * 2) = H;
            *(uint32_t*)(smem + SM_AL + (rl + 8) * ROW_B + cc * 2) = L;
        }
}

__device__ __forceinline__ void acc_store(float* __restrict__ out,
                                          float acc[2][4][4], int row0,
                                          int m0, int nwn, int g, int tig,
                                          int nrows) {
    const int rl = m0 + g;
    const int g0 = row0 + rl, g1 = g0 + 8;
    #pragma unroll
    for (int p = 0; p < 2; ++p)
        #pragma unroll
        for (int na = 0; na < 4; ++na) {
            int cc = p * 64 + nwn + na * 8 + 2 * tig;
            if (g0 < nrows)
                *(float2*)(out + (size_t)g0 * DD + cc) =
                    make_float2(acc[p][na][0], acc[p][na][1]);
            if (g1 < nrows)
                *(float2*)(out + (size_t)g1 * DD + cc) =
                    make_float2(acc[p][na][2], acc[p][na][3]);
        }
}

__device__ __forceinline__ void pre_add(float acc[2][4][4],
                                        const float* __restrict__ U,
                                        const float* __restrict__ V,
                                        const int* s_ia, const int* s_ib,
                                        int row0, int m0, int nwn, int g,
                                        int tig, int nrows) {
    const int rl = m0 + g;
    #pragma unroll
    for (int half = 0; half < 2; ++half) {
        int rloc = rl + half * 8;
        int grow = row0 + rloc;
        if (grow < nrows) {
            const float* pu = U + (size_t)s_ia[rloc] * DD;
            const float* pv = V + (size_t)s_ib[rloc] * DD;
            #pragma unroll
            for (int p = 0; p < 2; ++p)
                #pragma unroll
                for (int na = 0; na < 4; ++na) {
                    int cc = p * 64 + nwn + na * 8 + 2 * tig;
                    float2 va = *(const float2*)(pu + cc);
                    float2 vb = *(const float2*)(pv + cc);
                    acc[p][na][half * 2 + 0] += va.x + vb.x;
                    acc[p][na][half * 2 + 1] += va.y + vb.y;
                }
        }
    }
}

// ---------------- small utility kernels ------------------------------------
__global__ void convert_idx_kernel(const void* __restrict__ raw,
                                   int* __restrict__ st, int* __restrict__ en,
                                   int E) {
    __shared__ int s_is64;
    if (threadIdx.x == 0) {
        const unsigned int* w = (const unsigned int*)raw;
        unsigned int acc = 0;
        #pragma unroll 8
        for (int i = 0; i < 128; ++i) acc |= w[2 * i + 1];
        s_is64 = (acc == 0u);
    }
    __syncthreads();
    const int is64 = s_is64;
    int i = blockIdx.x * blockDim.x + threadIdx.x;
    if (i >= 2 * E) return;
    int v;
    if (is64) v = (int)((const long long*)raw)[i];
    else      v = ((const int*)raw)[i];
    if (i < E) st[i] = v; else en[i - E] = v;
}

// 0:ne_W1(k<16) 1:ne_W2  2-3:ee_W1(a,b) 4:ee_W2  5-6:nn_W1 7:nn_W2
// 8-10:en_W1(a,b,c) 11:en_W2  12-14:pe_W1(a,b,c)
__global__ void pack_w_kernel(const float* neW1, const float* neW2,
                              const float* eeW1, const float* eeW2,
                              const float* nnW1, const float* nnW2,
                              const float* enW1, const float* enW2,
                              const float* peW1,
                              __nv_bfloat16* gh, __nv_bfloat16* gl) {
    int t = blockIdx.x * blockDim.x + threadIdx.x;
    if (t >= 15 * 16384) return;
    int chunk = t >> 14;
    int e = t & 16383;
    int k = e & 127;
    int n = e >> 7;
    const float* W; int koff = 0; int kvalid = 128;
    switch (chunk) {
        case 0:  W = neW1; kvalid = 16; break;
        case 1:  W = neW2; break;
        case 2: case 3:  W = eeW1; koff = (chunk - 2) * 128; break;
        case 4:  W = eeW2; break;
        case 5: case 6:  W = nnW1; koff = (chunk - 5) * 128; break;
        case 7:  W = nnW2; break;
        case 8: case 9: case 10: W = enW1; koff = (chunk - 8) * 128; break;
        case 11: W = enW2; break;
        default: W = peW1; koff = (chunk - 12) * 128; break;
    }
    float x = (k < kvalid) ? W[(size_t)(koff + k) * 128 + n] : 0.f;
    __nv_bfloat16 h = __float2bfloat16(x);
    __nv_bfloat16 l = __float2bfloat16(x - __bfloat162float(h));
    gh[(size_t)chunk * 16384 + n * 128 + k] = h;
    gl[(size_t)chunk * 16384 + n * 128 + k] = l;
}

// ---------------------------------------------------------------------------
// Fused node kernel (full: used for initial ne+Pa/Pb and last-iter nn+Q+R).
// ---------------------------------------------------------------------------
template <int NCH, int KS1, bool PRE2, bool POST2, bool RES>
__global__ void __launch_bounds__(256, 3)
node_fused(const float* __restrict__ s0, const float* __restrict__ s1,
           int wqa, int wqb, float* __restrict__ Qa, float* __restrict__ Qb,
           int w1c0, int w2c,
           int wra, int wrb, float* __restrict__ Ra, float* __restrict__ Rb,
           const float* __restrict__ b1, const float* __restrict__ b2,
           const float* __restrict__ res, float* __restrict__ out,
           float* __restrict__ zrow, int nrows) {
    extern __shared__ char smem[];
    const uint32_t sb = smem_u32(smem);
    const int tid = threadIdx.x, lane = tid & 31, wid = tid >> 5;
    const int row0 = blockIdx.x * 64;
    const int g = lane >> 2, tig = lane & 3;
    const int m0 = (wid >> 1) * 16;
    const int nwn = (wid & 1) * 32;
    const int a_ro = (lane & 7) + ((lane >> 3) & 1) * 8;
    const int a_co = ((lane >> 4) & 1) * 8;
    const int b_ro = (lane & 7) + ((lane >> 4) & 1) * 8;
    const int b_co = ((lane >> 3) & 1) * 8;

    float* b1s = (float*)(smem + SM_B1);
    float* b2s = (float*)(smem + SM_B2);
    if (tid < 128) { b1s[tid] = b1[tid]; b2s[tid] = b2[tid]; }

    copyw_half(sb, tid, PRE2 ? wqa : w1c0, 0);

    if (zrow != nullptr) {
        float4* zp = (float4*)(zrow + (size_t)row0 * DD);
        int nz = (nrows - row0 < 64 ? nrows - row0 : 64) * 32;
        for (int i = tid; i < nz; i += 256)
            zp[i] = make_float4(0.f, 0.f, 0.f, 0.f);
    }

    stage_a<KS1 * 16>(smem, wid, lane, row0, s0, nrows);

    float acc[2][4][4];

    if constexpr (PRE2) {
        zacc2(acc);
        layer_gemm_issued<KS1>(sb, tid, wqa, m0, nwn, a_ro, a_co, b_ro, b_co, acc);
        __syncthreads();
        copyw_half(sb, tid, wqb, 0);
        acc_store(Qa, acc, row0, m0, nwn, g, tig, nrows);
        zacc2(acc);
        layer_gemm_issued<KS1>(sb, tid, wqb, m0, nwn, a_ro, a_co, b_ro, b_co, acc);
        __syncthreads();
        copyw_half(sb, tid, w1c0, 0);
        acc_store(Qb, acc, row0, m0, nwn, g, tig, nrows);
    }

    zacc2(acc);
    layer_gemm_issued<KS1>(sb, tid, w1c0, m0, nwn, a_ro, a_co, b_ro, b_co, acc);

    if constexpr (NCH == 2) {
        __syncthreads();
        copyw_half(sb, tid, w1c0 + 1, 0);
        stage_a<128>(smem, wid, lane, row0, s1, nrows);
        layer_gemm_issued<8>(sb, tid, w1c0 + 1, m0, nwn, a_ro, a_co, b_ro, b_co, acc);
    }

    __syncthreads();
    copyw_half(sb, tid, w2c, 0);
    acc_to_A(smem, acc, m0, nwn, g, tig, b1s, true);

    zacc2(acc);
    layer_gemm_issued<8>(sb, tid, w2c, m0, nwn, a_ro, a_co, b_ro, b_co, acc);

    {
        const int rl = m0 + g;
        #pragma unroll
        for (int half = 0; half < 2; ++half) {
            int grow = row0 + rl + half * 8;
            #pragma unroll
            for (int p = 0; p < 2; ++p)
                #pragma unroll
                for (int na = 0; na < 4; ++na) {
                    int cc = p * 64 + nwn + na * 8 + 2 * tig;
                    float bx = b2s[cc], by = b2s[cc + 1];
                    float rx = 0.f, ry = 0.f;
                    if (RES && grow < nrows) {
                        float2 rv = *(const float2*)(res + (size_t)grow * DD + cc);
                        rx = rv.x; ry = rv.y;
                    }
                    acc[p][na][half * 2 + 0] += bx + rx;
                    acc[p][na][half * 2 + 1] += by + ry;
                }
        }
    }

    if constexpr (POST2) {
        __syncthreads();
        copyw_half(sb, tid, wra, 0);
        acc_store(out, acc, row0, m0, nwn, g, tig, nrows);
        acc_to_A(smem, acc, m0, nwn, g, tig, nullptr, false);
        zacc2(acc);
        layer_gemm_issued<8>(sb, tid, wra, m0, nwn, a_ro, a_co, b_ro, b_co, acc);
        __syncthreads();
        copyw_half(sb, tid, wrb, 0);
        acc_store(Ra, acc, row0, m0, nwn, g, tig, nrows);
        zacc2(acc);
        layer_gemm_issued<8>(sb, tid, wrb, m0, nwn, a_ro, a_co, b_ro, b_co, acc);
        acc_store(Rb, acc, row0, m0, nwn, g, tig, nrows);
    } else {
        acc_store(out, acc, row0, m0, nwn, g, tig, nrows);
    }
}

// ---------------------------------------------------------------------------
// node_q: Qa = hA@W[8], Qb = hA@W[9]; also zeroes zrow rows (next msg buffer).
// ---------------------------------------------------------------------------
__global__ void __launch_bounds__(256, 3)
node_q(const float* __restrict__ s0, float* __restrict__ Qa,
       float* __restrict__ Qb, float* __restrict__ zrow, int nrows) {
    extern __shared__ char smem[];
    const uint32_t sb = smem_u32(smem);
    const int tid = threadIdx.x, lane = tid & 31, wid = tid >> 5;
    const int row0 = blockIdx.x * 64;
    const int g = lane >> 2, tig = lane & 3;
    const int m0 = (wid >> 1) * 16;
    const int nwn = (wid & 1) * 32;
    const int a_ro = (lane & 7) + ((lane >> 3) & 1) * 8;
    const int a_co = ((lane >> 4) & 1) * 8;
    const int b_ro = (lane & 7) + ((lane >> 4) & 1) * 8;
    const int b_co = ((lane >> 3) & 1) * 8;

    copyw_half(sb, tid, 8, 0);

    {
        float4* zp = (float4*)(zrow + (size_t)row0 * DD);
        int nz = (nrows - row0 < 64 ? nrows - row0 : 64) * 32;
        for (int i = tid; i < nz; i += 256)
            zp[i] = make_float4(0.f, 0.f, 0.f, 0.f);
    }

    stage_a<128>(smem, wid, lane, row0, s0, nrows);

    float acc[2][4][4];
    zacc2(acc);
    layer_gemm_issued<8>(sb, tid, 8, m0, nwn, a_ro, a_co, b_ro, b_co, acc);
    __syncthreads();
    copyw_half(sb, tid, 9, 0);
    acc_store(Qa, acc, row0, m0, nwn, g, tig, nrows);
    zacc2(acc);
    layer_gemm_issued<8>(sb, tid, 9, m0, nwn, a_ro, a_co, b_ro, b_co, acc);
    acc_store(Qb, acc, row0, m0, nwn, g, tig, nrows);
}

// ---------------------------------------------------------------------------
// edge body (en path with scatter) — R10 logic, full K=128 layer 1.
// ---------------------------------------------------------------------------
__device__ __forceinline__ void edge_en_body(
    char* smem, uint32_t sb, int tid, int lane, int wid, int row0,
    const float* __restrict__ e,
    const int* __restrict__ ip0, const int* __restrict__ ip1,
    const float* __restrict__ Qa, const float* __restrict__ Qb,
    const float* __restrict__ b1, const float* __restrict__ b2,
    float* __restrict__ out, float* __restrict__ msgout) {
    const int g = lane >> 2, tig = lane & 3;
    const int m0 = (wid >> 1) * 16;
    const int nwn = (wid & 1) * 32;
    const int a_ro = (lane & 7) + ((lane >> 3) & 1) * 8;
    const int a_co = ((lane >> 4) & 1) * 8;
    const int b_ro = (lane & 7) + ((lane >> 4) & 1) * 8;
    const int b_co = ((lane >> 3) & 1) * 8;

    float* b1s = (float*)(smem + SM_B1);
    float* b2s = (float*)(smem + SM_B2);
    int*   s_ia = (int*)(smem + SM_IA);
    int*   s_ib = (int*)(smem + SM_IB);

    copyw_half(sb, tid, 10, 0);

    if (tid < 128) { b1s[tid] = b1[tid]; b2s[tid] = b2[tid]; }
    if (tid < 64) {
        int ia = ip0[row0 + tid], ib = ip1[row0 + tid];
        s_ia[tid] = ia; s_ib[tid] = ib;
        const char* pa = (const char*)(Qa + (size_t)ia * DD);
        const char* pb = (const char*)(Qb + (size_t)ib * DD);
        #pragma unroll
        for (int l = 0; l < 4; ++l) {
            asm volatile("prefetch.global.L2 [%0];" :: "l"(pa + l * 128));
            asm volatile("prefetch.global.L2 [%0];" :: "l"(pb + l * 128));
        }
    }

    float acc[2][4][4];
    zacc2(acc);

    stage_a<128>(smem, wid, lane, row0, e, N_EDGES);
    layer_gemm_issued<8>(sb, tid, 10, m0, nwn, a_ro, a_co, b_ro, b_co, acc);
    pre_add(acc, Qa, Qb, s_ia, s_ib, row0, m0, nwn, g, tig, N_EDGES);

    __syncthreads();
    copyw_half(sb, tid, 11, 0);
    acc_to_A(smem, acc, m0, nwn, g, tig, b1s, true);
    zacc2(acc);
    layer_gemm_issued<8>(sb, tid, 11, m0, nwn, a_ro, a_co, b_ro, b_co, acc);

    // epilogue: out = acc + b2 + e residual; also stage for scatter
    __syncthreads();      // all warps done reading A/B tiles
    float* stg = (float*)(smem + SM_STG);
    const int rl = m0 + g;
    #pragma unroll
    for (int half = 0; half < 2; ++half) {
        int rloc = rl + half * 8;
        int grow = row0 + rloc;
        #pragma unroll
        for (int p = 0; p < 2; ++p)
            #pragma unroll
            for (int na = 0; na < 4; ++na) {
                int cc = p * 64 + nwn + na * 8 + 2 * tig;
                float2 rv = *(const float2*)(e + (size_t)grow * DD + cc);
                float ox = acc[p][na][half * 2 + 0] + b2s[cc] + rv.x;
                float oy = acc[p][na][half * 2 + 1] + b2s[cc + 1] + rv.y;
                float2 o = make_float2(ox, oy);
                *(float2*)(out + (size_t)grow * DD + cc) = o;
                *(float2*)(stg + rloc * DD + cc) = o;
            }
    }
    __syncthreads();
    asm volatile("fence.proxy.async.shared::cta;" ::: "memory");
    if (tid < 64) {
        uint32_t src = sb + SM_STG + tid * 512;
        float* dst = msgout + (size_t)s_ib[tid] * DD;
        asm volatile(
            "cp.reduce.async.bulk.global.shared::cta.bulk_group.add.f32 "
            "[%0], [%1], 512;"
            :: "l"(dst), "r"(src) : "memory");
    }
    asm volatile("cp.async.bulk.commit_group;" ::: "memory");
    asm volatile("cp.async.bulk.wait_group 0;" ::: "memory");
}

// ---------------------------------------------------------------------------
// node_nn body: h' = relu((hA||mcur)@nnW1 + b1)@nnW2 + b2 + hA  -> hB
// ---------------------------------------------------------------------------
__device__ __forceinline__ void node_nn_body(
    char* smem, uint32_t sb, int tid, int lane, int wid, int row0,
    const float* __restrict__ hA, const float* __restrict__ mcur,
    const float* __restrict__ b1, const float* __restrict__ b2,
    float* __restrict__ hB) {
    const int g = lane >> 2, tig = lane & 3;
    const int m0 = (wid >> 1) * 16;
    const int nwn = (wid & 1) * 32;
    const int a_ro = (lane & 7) + ((lane >> 3) & 1) * 8;
    const int a_co = ((lane >> 4) & 1) * 8;
    const int b_ro = (lane & 7) + ((lane >> 4) & 1) * 8;
    const int b_co = ((lane >> 3) & 1) * 8;

    float* b1s = (float*)(smem + SM_B1);
    float* b2s = (float*)(smem + SM_B2);
    if (tid < 128) { b1s[tid] = b1[tid]; b2s[tid] = b2[tid]; }

    copyw_half(sb, tid, 5, 0);
    stage_a<128>(smem, wid, lane, row0, hA, N_NODES);

    float acc[2][4][4];
    zacc2(acc);
    layer_gemm_issued<8>(sb, tid, 5, m0, nwn, a_ro, a_co, b_ro, b_co, acc);

    __syncthreads();
    copyw_half(sb, tid, 6, 0);
    stage_a<128>(smem, wid, lane, row0, mcur, N_NODES);
    layer_gemm_issued<8>(sb, tid, 6, m0, nwn, a_ro, a_co, b_ro, b_co, acc);

    __syncthreads();
    copyw_half(sb, tid, 7, 0);
    acc_to_A(smem, acc, m0, nwn, g, tig, b1s, true);
    zacc2(acc);
    layer_gemm_issued<8>(sb, tid, 7, m0, nwn, a_ro, a_co, b_ro, b_co, acc);

    // fold b2 + residual hA, store hB
    const int rl = m0 + g;
    #pragma unroll
    for (int half = 0; half < 2; ++half) {
        int grow = row0 + rl + half * 8;
        if (grow < N_NODES) {
            #pragma unroll
            for (int p = 0; p < 2; ++p)
                #pragma unroll
                for (int na = 0; na < 4; ++na) {
                    int cc = p * 64 + nwn + na * 8 + 2 * tig;
                    float2 rv = *(const float2*)(hA + (size_t)grow * DD + cc);
                    float ox = acc[p][na][half * 2 + 0] + b2s[cc] + rv.x;
                    float oy = acc[p][na][half * 2 + 1] + b2s[cc + 1] + rv.y;
                    *(float2*)(hB + (size_t)grow * DD + cc) = make_float2(ox, oy);
                }
        }
    }
}

// ---------------------------------------------------------------------------
// Fused edge(en)+node_nn launch: blocks [0,EBLK) = edge, [EBLK,EBLK+NBLK) = nn.
// ---------------------------------------------------------------------------
__global__ void __launch_bounds__(256, 3)
edge_nn_fused(const float* __restrict__ e,
              const int* __restrict__ ip0, const int* __restrict__ ip1,
              const float* __restrict__ Qa, const float* __restrict__ Qb,
              const float* __restrict__ en_b1, const float* __restrict__ en_b2,
              float* __restrict__ eout, float* __restrict__ msgout,
              const float* __restrict__ hA, const float* __restrict__ mcur,
              const float* __restrict__ nn_b1, const float* __restrict__ nn_b2,
              float* __restrict__ hB) {
    extern __shared__ char smem[];
    const uint32_t sb = smem_u32(smem);
    const int tid = threadIdx.x, lane = tid & 31, wid = tid >> 5;
    if (blockIdx.x < EBLK) {
        edge_en_body(smem, sb, tid, lane, wid, blockIdx.x * 64,
                     e, ip0, ip1, Qa, Qb, en_b1, en_b2, eout, msgout);
    } else {
        node_nn_body(smem, sb, tid, lane, wid, (blockIdx.x - EBLK) * 64,
                     hA, mcur, nn_b1, nn_b2, hB);
    }
}

// ---------------------------------------------------------------------------
// Edge kernel (ee path: no layer-1 GEMM, with scatter) — standalone.
// ---------------------------------------------------------------------------
__global__ void __launch_bounds__(256, 3)
edge_ee(const int* __restrict__ ip0, const int* __restrict__ ip1,
        const float* __restrict__ Pa, const float* __restrict__ Pb,
        const float* __restrict__ b1, const float* __restrict__ b2,
        float* __restrict__ out, float* __restrict__ msgout) {
    extern __shared__ char smem[];
    const uint32_t sb = smem_u32(smem);
    const int tid = threadIdx.x, lane = tid & 31, wid = tid >> 5;
    const int row0 = blockIdx.x * 64;
    const int g = lane >> 2, tig = lane & 3;
    const int m0 = (wid >> 1) * 16;
    const int nwn = (wid & 1) * 32;
    const int a_ro = (lane & 7) + ((lane >> 3) & 1) * 8;
    const int a_co = ((lane >> 4) & 1) * 8;
    const int b_ro = (lane & 7) + ((lane >> 4) & 1) * 8;
    const int b_co = ((lane >> 3) & 1) * 8;

    float* b1s = (float*)(smem + SM_B1);
    float* b2s = (float*)(smem + SM_B2);
    int*   s_ia = (int*)(smem + SM_IA);
    int*   s_ib = (int*)(smem + SM_IB);

    copyw_half(sb, tid, 4, 0);   // eeW2

    if (tid < 128) { b1s[tid] = b1[tid]; b2s[tid] = b2[tid]; }
    if (tid < 64) {
        int ia = ip0[row0 + tid], ib = ip1[row0 + tid];
        s_ia[tid] = ia; s_ib[tid] = ib;
        const char* pa = (const char*)(Pa + (size_t)ia * DD);
        const char* pb = (const char*)(Pb + (size_t)ib * DD);
        #pragma unroll
        for (int l = 0; l < 4; ++l) {
            asm volatile("prefetch.global.L2 [%0];" :: "l"(pa + l * 128));
            asm volatile("prefetch.global.L2 [%0];" :: "l"(pb + l * 128));
        }
    }
    __syncthreads();

    float acc[2][4][4];
    zacc2(acc);
    pre_add(acc, Pa, Pb, s_ia, s_ib, row0, m0, nwn, g, tig, N_EDGES);

    acc_to_A(smem, acc, m0, nwn, g, tig, b1s, true);
    zacc2(acc);
    layer_gemm_issued<8>(sb, tid, 4, m0, nwn, a_ro, a_co, b_ro, b_co, acc);

    __syncthreads();
    float* stg = (float*)(smem + SM_STG);
    const int rl = m0 + g;
    #pragma unroll
    for (int half = 0; half < 2; ++half) {
        int rloc = rl + half * 8;
        int grow = row0 + rloc;
        #pragma unroll
        for (int p = 0; p < 2; ++p)
            #pragma unroll
            for (int na = 0; na < 4; ++na) {
                int cc = p * 64 + nwn + na * 8 + 2 * tig;
                float ox = acc[p][na][half * 2 + 0] + b2s[cc];
                float oy = acc[p][na][half * 2 + 1] + b2s[cc + 1];
                float2 o = make_float2(ox, oy);
                *(float2*)(out + (size_t)grow * DD + cc) = o;
                *(float2*)(stg + rloc * DD + cc) = o;
            }
    }
    __syncthreads();
    asm volatile("fence.proxy.async.shared::cta;" ::: "memory");
    if (tid < 64) {
        uint32_t src = sb + SM_STG + tid * 512;
        float* dst = msgout + (size_t)s_ib[tid] * DD;
        asm volatile(
            "cp.reduce.async.bulk.global.shared::cta.bulk_group.add.f32 "
            "[%0], [%1], 512;"
            :: "l"(dst), "r"(src) : "memory");
    }
    asm volatile("cp.async.bulk.commit_group;" ::: "memory");
    asm volatile("cp.async.bulk.wait_group 0;" ::: "memory");
}

// ---------------------------------------------------------------------------
// Fused final edge kernel (R10): e_new in registers, then pe layer + dot.
// ---------------------------------------------------------------------------
__global__ void __launch_bounds__(256, 3)
edge_en_pe(const float* __restrict__ e,
           const int* __restrict__ ip0, const int* __restrict__ ip1,
           const float* __restrict__ Qa, const float* __restrict__ Qb,
           const float* __restrict__ Ra, const float* __restrict__ Rb,
           const float* __restrict__ en_b1, const float* __restrict__ en_b2,
           const float* __restrict__ pe_b1v, const float* __restrict__ pe_b2v,
           const float* __restrict__ pe_w2v,
           float* __restrict__ pred, int nrows) {
    extern __shared__ char smem[];
    const uint32_t sb = smem_u32(smem);
    const int tid = threadIdx.x, lane = tid & 31, wid = tid >> 5;
    const int row0 = blockIdx.x * 64;
    const int g = lane >> 2, tig = lane & 3;
    const int m0 = (wid >> 1) * 16;
    const int nwn = (wid & 1) * 32;
    const int a_ro = (lane & 7) + ((lane >> 3) & 1) * 8;
    const int a_co = ((lane >> 4) & 1) * 8;
    const int b_ro = (lane & 7) + ((lane >> 4) & 1) * 8;
    const int b_co = ((lane >> 3) & 1) * 8;

    float* b1s = (float*)(smem + SM_B1);
    float* b2s = (float*)(smem + SM_B2);
    float* b1p = (float*)(smem + SM_B1P);
    float* w2s = (float*)(smem + SM_W2V);
    int*   s_ia = (int*)(smem + SM_IA);
    int*   s_ib = (int*)(smem + SM_IB);

    copyw_half(sb, tid, 10, 0);

    if (tid < 128) {
        b1s[tid] = en_b1[tid];
        b2s[tid] = en_b2[tid];
        b1p[tid] = pe_b1v[tid];
        w2s[tid] = pe_w2v[tid];
    }
    if (tid < 64) {
        int grow = row0 + tid;
        int ia = 0, ib = 0;
        if (grow < nrows) { ia = ip0[grow]; ib = ip1[grow]; }
        s_ia[tid] = ia; s_ib[tid] = ib;
        const char* qa = (const char*)(Qa + (size_t)ia * DD);
        const char* qb = (const char*)(Qb + (size_t)ib * DD);
        const char* ra = (const char*)(Ra + (size_t)ia * DD);
        const char* rb = (const char*)(Rb + (size_t)ib * DD);
        #pragma unroll
        for (int l = 0; l < 4; ++l) {
            asm volatile("prefetch.global.L2 [%0];" :: "l"(qa + l * 128));
            asm volatile("prefetch.global.L2 [%0];" :: "l"(qb + l * 128));
            asm volatile("prefetch.global.L2 [%0];" :: "l"(ra + l * 128));
            asm volatile("prefetch.global.L2 [%0];" :: "l"(rb + l * 128));
        }
    }

    float acc[2][4][4];
    zacc2(acc);

    stage_a<128>(smem, wid, lane, row0, e, nrows);
    layer_gemm_issued<8>(sb, tid, 10, m0, nwn, a_ro, a_co, b_ro, b_co, acc);
    pre_add(acc, Qa, Qb, s_ia, s_ib, row0, m0, nwn, g, tig, nrows);

    __syncthreads();
    copyw_half(sb, tid, 11, 0);
    acc_to_A(smem, acc, m0, nwn, g, tig, b1s, true);
    zacc2(acc);
    layer_gemm_issued<8>(sb, tid, 11, m0, nwn, a_ro, a_co, b_ro, b_co, acc);

    {
        const int rl = m0 + g;
        #pragma unroll
        for (int half = 0; half < 2; ++half) {
            int grow = row0 + rl + half * 8;
            if (grow < nrows) {
                #pragma unroll
                for (int p = 0; p < 2; ++p)
                    #pragma unroll
                    for (int na = 0; na < 4; ++na) {
                        int cc = p * 64 + nwn + na * 8 + 2 * tig;
                        float2 rv = *(const float2*)(e + (size_t)grow * DD + cc);
                        acc[p][na][half * 2 + 0] += b2s[cc] + rv.x;
                        acc[p][na][half * 2 + 1] += b2s[cc + 1] + rv.y;
                    }
            }
        }
    }

    __syncthreads();
    copyw_half(sb, tid, 14, 0);
    acc_to_A(smem, acc, m0, nwn, g, tig, nullptr, false);
    zacc2(acc);
    layer_gemm_issued<8>(sb, tid, 14, m0, nwn, a_ro, a_co, b_ro, b_co, acc);
    pre_add(acc, Ra, Rb, s_ia, s_ib, row0, m0, nwn, g, tig, nrows);

    float* hT = (float*)(smem + SM_AH);
    __syncthreads();
    {
        const int rl = m0 + g;
        #pragma unroll
        for (int p = 0; p < 2; ++p)
            #pragma unroll
            for (int na = 0; na < 4; ++na) {
                int cc = p * 64 + nwn + na * 8 + 2 * tig;
                hT[rl * 129 + cc]           = fmaxf(acc[p][na][0] + b1p[cc], 0.f);
                hT[rl * 129 + cc + 1]       = fmaxf(acc[p][na][1] + b1p[cc + 1], 0.f);
                hT[(rl + 8) * 129 + cc]     = fmaxf(acc[p][na][2] + b1p[cc], 0.f);
                hT[(rl + 8) * 129 + cc + 1] = fmaxf(acc[p][na][3] + b1p[cc + 1], 0.f);
            }
    }
    __syncthreads();
    if (tid < 64) {
        int grow = row0 + tid;
        float a = __ldg(&pe_b2v[0]);
        #pragma unroll 8
        for (int k = 0; k < 128; ++k) a += hT[tid * 129 + k] * w2s[k];
        if (grow < nrows) pred[grow] = a;
    }
}

// ---------------------------------------------------------------------------
extern "C" void kernel_launch(void* const* d_in, const int* in_sizes, int n_in,
                              void* d_out, int out_size) {
    const float* nodes = (const float*)d_in[0];
    const void*  eidx  = d_in[1];
    const float* ne_W1 = (const float*)d_in[2];
    const float* ne_b1 = (const float*)d_in[3];
    const float* ne_W2 = (const float*)d_in[4];
    const float* ne_b2 = (const float*)d_in[5];
    const float* ee_W1 = (const float*)d_in[6];
    const float* ee_b1 = (const float*)d_in[7];
    const float* ee_W2 = (const float*)d_in[8];
    const float* ee_b2 = (const float*)d_in[9];
    const float* nn_W1 = (const float*)d_in[10];
    const float* nn_b1 = (const float*)d_in[11];
    const float* nn_W2 = (const float*)d_in[12];
    const float* nn_b2 = (const float*)d_in[13];
    const float* en_W1 = (const float*)d_in[14];
    const float* en_b1 = (const float*)d_in[15];
    const float* en_W2 = (const float*)d_in[16];
    const float* en_b2 = (const float*)d_in[17];
    const float* pe_W1 = (const float*)d_in[18];
    const float* pe_b1 = (const float*)d_in[19];
    const float* pe_W2 = (const float*)d_in[20];
    const float* pe_b2 = (const float*)d_in[21];

    float *h, *h2, *m0, *m1, *e, *pa, *pb, *pc, *pd;
    int *st, *en_;
    __nv_bfloat16 *pwh, *pwl;
    cudaGetSymbolAddress((void**)&h,   g_h);
    cudaGetSymbolAddress((void**)&h2,  g_h2);
    cudaGetSymbolAddress((void**)&m0,  g_m0);
    cudaGetSymbolAddress((void**)&m1,  g_m1);
    cudaGetSymbolAddress((void**)&e,   g_e);
    cudaGetSymbolAddress((void**)&pa,  g_pa);
    cudaGetSymbolAddress((void**)&pb,  g_pb);
    cudaGetSymbolAddress((void**)&pc,  g_pc);
    cudaGetSymbolAddress((void**)&pd,  g_pd);
    cudaGetSymbolAddress((void**)&st,  g_start);
    cudaGetSymbolAddress((void**)&en_, g_end);
    cudaGetSymbolAddress((void**)&pwh, g_pwh);
    cudaGetSymbolAddress((void**)&pwl, g_pwl);

    cudaFuncSetAttribute(node_fused<1, 1, false, true, false>,
                         cudaFuncAttributeMaxDynamicSharedMemorySize, SM_TOTAL);
    cudaFuncSetAttribute(node_fused<2, 8, true, true, true>,
                         cudaFuncAttributeMaxDynamicSharedMemorySize, SM_TOTAL);
    cudaFuncSetAttribute(node_q,
                         cudaFuncAttributeMaxDynamicSharedMemorySize, SM_TOTAL);
    cudaFuncSetAttribute(edge_ee,
                         cudaFuncAttributeMaxDynamicSharedMemorySize, SM_TOTAL);
    cudaFuncSetAttribute(edge_nn_fused,
                         cudaFuncAttributeMaxDynamicSharedMemorySize, SM_TOTAL);
    cudaFuncSetAttribute(edge_en_pe,
                         cudaFuncAttributeMaxDynamicSharedMemorySize, SM_TOTAL);

    convert_idx_kernel<<<(2 * N_EDGES + 255) / 256, 256>>>(eidx, st, en_, N_EDGES);
    pack_w_kernel<<<(15 * 16384 + 255) / 256, 256>>>(
        ne_W1, ne_W2, ee_W1, ee_W2, nn_W1, nn_W2, en_W1, en_W2, pe_W1, pwh, pwl);

    // h = MLP_ne(nodes);  Pa = h@eeW1a, Pb = h@eeW1b;  zero m0
    node_fused<1, 1, false, true, false><<<NBLK, 256, SM_TOTAL>>>(
        nodes, nullptr, 0, 0, nullptr, nullptr, 0, 1,
        2, 3, pa, pb, ne_b1, ne_b2, nullptr, h, m0, N_NODES);

    // e = relu(Pa[s]+Pb[e]+b1)@eeW2 + b2;  scatter e -> m0
    edge_ee<<<EBLK, 256, SM_TOTAL>>>(st, en_, pa, pb, ee_b1, ee_b2, e, m0);

    float* hA = h;
    float* hB = h2;
    float* msgs[2] = {m0, m1};

    for (int it = 0; it < NUM_ITERS; ++it) {
        float* mcur = msgs[it & 1];
        float* mnxt = msgs[(it + 1) & 1];
        const bool last = (it == NUM_ITERS - 1);

        if (!last) {
            // critical path: Qa/Qb from hA; zero mnxt
            node_q<<<NBLK, 256, SM_TOTAL>>>(hA, pa, pb, mnxt, N_NODES);
            // overlapped: edge(en) + node_nn in one launch
            edge_nn_fused<<<EBLK + NBLK, 256, SM_TOTAL>>>(
                e, st, en_, pa, pb, en_b1, en_b2, e, mnxt,
                hA, mcur, nn_b1, nn_b2, hB);
        } else {
            // last iteration: full serial node (Q + nn + R), then fused en+pe
            node_fused<2, 8, true, true, true><<<NBLK, 256, SM_TOTAL>>>(
                hA, mcur, 8, 9, pa, pb, 5, 7,
                12, 13, pc, pd, nn_b1, nn_b2, hA, hB, nullptr, N_NODES);

            edge_en_pe<<<EBLK, 256, SM_TOTAL>>>(
                e, st, en_, pa, pb, pc, pd,
                en_b1, en_b2, pe_b1, pe_b2, pe_W2,
                (float*)d_out, N_EDGES);
        }

        float* t = hA; hA = hB; hB = t;
    }
}

// round 14
// speedup vs baseline: 1.0468x; 1.0468x over previous
#include <cuda_runtime.h>
#include <cuda_bf16.h>
#include <cstdint>

// ---------------------------------------------------------------------------
// InteractionGNN on GB300 — round 14: R10 base (best) + smem-staged gathers
// in edge kernels (coalesced Pa/Pb loads + padded-smem fragment reads replace
// scattered per-fragment LDGs; ~20% L1 wavefront cut on edge kernels).
// GEMM core: mma.sync bf16 3-term split (Ah*Wh + Ah*Wl + Al*Wh), fp32 accum.
// ---------------------------------------------------------------------------

#define N_NODES 100000
#define N_EDGES 600000
#define DD      128
#define NUM_ITERS 4

// ---------------- device scratch -------------------------------------------
__device__ float g_h  [(size_t)N_NODES * DD];
__device__ float g_h2 [(size_t)N_NODES * DD];
__device__ float g_m0 [(size_t)N_NODES * DD];
__device__ float g_m1 [(size_t)N_NODES * DD];
__device__ float g_e  [(size_t)N_EDGES * DD];
__device__ float g_pa [(size_t)N_NODES * DD];
__device__ float g_pb [(size_t)N_NODES * DD];
__device__ float g_pc [(size_t)N_NODES * DD];
__device__ float g_pd [(size_t)N_NODES * DD];
__device__ int   g_start[N_EDGES];
__device__ int   g_end  [N_EDGES];
// prepacked weights: 15 chunks x [128 n][128 k] bf16, hi and lo images
__device__ __nv_bfloat16 g_pwh[15 * 16384];
__device__ __nv_bfloat16 g_pwl[15 * 16384];

// ---------------- smem layout ------------------------------------------------
static constexpr int ROW_B  = 272;
static constexpr int SM_B1  = 64;     // 128 f32
static constexpr int SM_W2V = 576;    // 128 f32
static constexpr int SM_B2  = 1088;   // 128 f32
static constexpr int SM_B1P = 1600;   // 128 f32 (pe_b1 in fused kernel)
static constexpr int SM_IA  = 2112;   // 64 ints
static constexpr int SM_IB  = 2368;   // 64 ints
static constexpr int SM_AH  = 2688;
static constexpr int TBUF   = 64 * ROW_B;          // 17408
static constexpr int SM_AL  = SM_AH + TBUF;        // 20096
static constexpr int SM_BH  = SM_AL + TBUF;        // 37504
static constexpr int SM_BL  = SM_BH + TBUF;        // 54912
static constexpr int SM_TOTAL = SM_BL + TBUF;      // 72320
// scatter staging: 64 rows x 512 B, overlaid on A tiles
static constexpr int SM_STG = SM_AH;
// gather staging: 64 rows x 544 B (PSTR=136 floats), overlaid on B tiles
static constexpr int SM_PST = SM_BH;               // 64*544 = 34816 = 2*TBUF
static constexpr int PSTR   = 136;                 // floats; 136%32==8 -> 2-way

// ---------------- helpers -----------------------------------------------------
__device__ __forceinline__ uint32_t smem_u32(const void* p) {
    uint32_t a;
    asm("{ .reg .u64 t; cvta.to.shared.u64 t, %1; cvt.u32.u64 %0, t; }"
        : "=r"(a) : "l"(p));
    return a;
}

#define LDSM_X4(R0, R1, R2, R3, ADDR) \
    asm volatile("ldmatrix.sync.aligned.m8n8.x4.shared.b16 {%0,%1,%2,%3}, [%4];" \
                 : "=r"(R0), "=r"(R1), "=r"(R2), "=r"(R3) : "r"(ADDR))

__device__ __forceinline__ void mma16816(float* c, const uint32_t* a,
                                         const uint32_t* b) {
    asm volatile(
        "mma.sync.aligned.m16n8k16.row.col.f32.bf16.bf16.f32 "
        "{%0,%1,%2,%3}, {%4,%5,%6,%7}, {%8,%9}, {%0,%1,%2,%3};"
        : "+f"(c[0]), "+f"(c[1]), "+f"(c[2]), "+f"(c[3])
        : "r"(a[0]), "r"(a[1]), "r"(a[2]), "r"(a[3]), "r"(b[0]), "r"(b[1]));
}

__device__ __forceinline__ uint32_t pack_bf2(float a, float b) {
    __nv_bfloat162 t = __floats2bfloat162_rn(a, b);
    return *reinterpret_cast<uint32_t*>(&t);
}

__device__ __forceinline__ void split2(float x, float y, uint32_t& H, uint32_t& L) {
    __nv_bfloat16 hx = __float2bfloat16(x);
    __nv_bfloat16 hy = __float2bfloat16(y);
    float lx = x - __bfloat162float(hx);
    float ly = y - __bfloat162float(hy);
    H = pack_bf2(__bfloat162float(hx), __bfloat162float(hy));
    L = pack_bf2(lx, ly);
}

#define CP_WAIT_ALL() asm volatile("cp.async.wait_group 0;" ::: "memory")

__device__ __forceinline__ void copyw_half(uint32_t sb, int tid, int chunk,
                                           int half) {
    const char* srcH = (const char*)(g_pwh + (size_t)chunk * 16384 + half * 8192);
    const char* srcL = (const char*)(g_pwl + (size_t)chunk * 16384 + half * 8192);
    #pragma unroll
    for (int i = tid; i < 1024; i += 256) {
        int rr = i >> 4, q = i & 15;
        uint32_t d = sb + SM_BH + rr * ROW_B + q * 16;
        asm volatile("cp.async.cg.shared.global [%0], [%1], 16;"
                     :: "r"(d), "l"(srcH + i * 16));
        asm volatile("cp.async.cg.shared.global [%0], [%1], 16;"
                     :: "r"(d + (uint32_t)TBUF), "l"(srcL + i * 16));
    }
    asm volatile("cp.async.commit_group;" ::: "memory");
}

template <int KSTEPS>
__device__ __forceinline__ void gemm3h(uint32_t sb, int m0, int nloc,
                                       int a_ro, int a_co, int b_ro, int b_co,
                                       float accp[4][4]) {
    #pragma unroll
    for (int ks = 0; ks < KSTEPS; ++ks) {
        const int k0 = ks * 16;
        uint32_t ah[4], al[4];
        {
            uint32_t ro = (uint32_t)(m0 + a_ro) * ROW_B + (uint32_t)(k0 + a_co) * 2;
            LDSM_X4(ah[0], ah[1], ah[2], ah[3], sb + SM_AH + ro);
            LDSM_X4(al[0], al[1], al[2], al[3], sb + SM_AL + ro);
        }
        uint32_t bh[4][2], bl[4][2];
        #pragma unroll
        for (int nb = 0; nb < 2; ++nb) {
            uint32_t ro = (uint32_t)(nloc + nb * 16 + b_ro) * ROW_B +
                          (uint32_t)(k0 + b_co) * 2;
            uint32_t r0, r1, r2, r3;
            LDSM_X4(r0, r1, r2, r3, sb + SM_BH + ro);
            bh[nb * 2][0] = r0; bh[nb * 2][1] = r1;
            bh[nb * 2 + 1][0] = r2; bh[nb * 2 + 1][1] = r3;
            LDSM_X4(r0, r1, r2, r3, sb + SM_BL + ro);
            bl[nb * 2][0] = r0; bl[nb * 2][1] = r1;
            bl[nb * 2 + 1][0] = r2; bl[nb * 2 + 1][1] = r3;
        }
        #pragma unroll
        for (int na = 0; na < 4; ++na) {
            mma16816(accp[na], ah, bh[na]);
            mma16816(accp[na], ah, bl[na]);
            mma16816(accp[na], al, bh[na]);
        }
    }
}

template <int KS>
__device__ __forceinline__ void layer_gemm_issued(uint32_t sb, int tid, int chunk,
                                                  int m0, int nloc,
                                                  int a_ro, int a_co,
                                                  int b_ro, int b_co,
                                                  float acc[2][4][4]) {
    CP_WAIT_ALL();
    __syncthreads();
    gemm3h<KS>(sb, m0, nloc, a_ro, a_co, b_ro, b_co, acc[0]);
    __syncthreads();
    copyw_half(sb, tid, chunk, 1);
    CP_WAIT_ALL();
    __syncthreads();
    gemm3h<KS>(sb, m0, nloc, a_ro, a_co, b_ro, b_co, acc[1]);
}

__device__ __forceinline__ void zacc2(float acc[2][4][4]) {
    #pragma unroll
    for (int q = 0; q < 32; ++q) (&acc[0][0][0])[q] = 0.f;
}

template <int SRC_K>
__device__ __forceinline__ void stage_a(char* smem, int wid, int lane, int row0,
                                        const float* __restrict__ src, int nrows) {
    for (int r = wid; r < 64; r += 8) {
        int grow = row0 + r;
        float4 v = make_float4(0.f, 0.f, 0.f, 0.f);
        if (grow < nrows && lane < SRC_K / 4)
            v = ((const float4*)(src + (size_t)grow * SRC_K))[lane];
        if (lane < SRC_K / 4) {
            uint32_t h0, l0, h1, l1;
            split2(v.x, v.y, h0, l0);
            split2(v.z, v.w, h1, l1);
            uint32_t off = r * ROW_B + lane * 8;
            *(uint2*)(smem + SM_AH + off) = make_uint2(h0, h1);
            *(uint2*)(smem + SM_AL + off) = make_uint2(l0, l1);
        }
    }
}

__device__ __forceinline__ void acc_to_A(char* smem, float acc[2][4][4],
                                         int m0, int nwn, int g, int tig,
                                         const float* b1s, bool relu) {
    const int rl = m0 + g;
    #pragma unroll
    for (int p = 0; p < 2; ++p)
        #pragma unroll
        for (int na = 0; na < 4; ++na) {
            int cc = p * 64 + nwn + na * 8 + 2 * tig;
            float bx = b1s ? b1s[cc] : 0.f;
            float by = b1s ? b1s[cc + 1] : 0.f;
            float v0 = acc[p][na][0] + bx, v1 = acc[p][na][1] + by;
            float v2 = acc[p][na][2] + bx, v3 = acc[p][na][3] + by;
            if (relu) {
                v0 = fmaxf(v0, 0.f); v1 = fmaxf(v1, 0.f);
                v2 = fmaxf(v2, 0.f); v3 = fmaxf(v3, 0.f);
            }
            uint32_t H, L;
            split2(v0, v1, H, L);
            *(uint32_t*)(smem + SM_AH + rl * ROW_B + cc * 2) = H;
            *(uint32_t*)(smem + SM_AL + rl * ROW_B + cc * 2) = L;
            split2(v2, v3, H, L);
            *(uint32_t*)(smem + SM_AH + (rl + 8) * ROW_B + cc * 2) = H;
            *(uint32_t*)(smem + SM_AL + (rl + 8) * ROW_B + cc * 2) = L;
        }
}

__device__ __forceinline__ void acc_store(float* __restrict__ out,
                                          float acc[2][4][4], int row0,
                                          int m0, int nwn, int g, int tig,
                                          int nrows) {
    const int rl = m0 + g;
    const int g0 = row0 + rl, g1 = g0 + 8;
    #pragma unroll
    for (int p = 0; p < 2; ++p)
        #pragma unroll
        for (int na = 0; na < 4; ++na) {
            int cc = p * 64 + nwn + na * 8 + 2 * tig;
            if (g0 < nrows)
                *(float2*)(out + (size_t)g0 * DD + cc) =
                    make_float2(acc[p][na][0], acc[p][na][1]);
            if (g1 < nrows)
                *(float2*)(out + (size_t)g1 * DD + cc) =
                    make_float2(acc[p][na][2], acc[p][na][3]);
        }
}

// ---- smem-staged gather: P = U[ia] + V[ib] into padded smem, then frag add --
__device__ __forceinline__ void stage_p(char* smem,
                                        const float* __restrict__ U,
                                        const float* __restrict__ V,
                                        const int* s_ia, const int* s_ib,
                                        int wid, int lane) {
    float* stp = (float*)(smem + SM_PST);
    #pragma unroll
    for (int r = wid; r < 64; r += 8) {
        const float4 va = ((const float4*)(U + (size_t)s_ia[r] * DD))[lane];
        const float4 vb = ((const float4*)(V + (size_t)s_ib[r] * DD))[lane];
        *(float4*)(stp + r * PSTR + lane * 4) =
            make_float4(va.x + vb.x, va.y + vb.y, va.z + vb.z, va.w + vb.w);
    }
}

__device__ __forceinline__ void pre_add_s(char* smem, float acc[2][4][4],
                                          int m0, int nwn, int g, int tig) {
    const float* stp = (const float*)(smem + SM_PST);
    const int rl = m0 + g;
    #pragma unroll
    for (int half = 0; half < 2; ++half) {
        const float* row = stp + (rl + half * 8) * PSTR;
        #pragma unroll
        for (int p = 0; p < 2; ++p)
            #pragma unroll
            for (int na = 0; na < 4; ++na) {
                int cc = p * 64 + nwn + na * 8 + 2 * tig;
                float2 v = *(const float2*)(row + cc);
                acc[p][na][half * 2 + 0] += v.x;
                acc[p][na][half * 2 + 1] += v.y;
            }
    }
}

// ---------------- small utility kernels ------------------------------------
__global__ void convert_idx_kernel(const void* __restrict__ raw,
                                   int* __restrict__ st, int* __restrict__ en,
                                   int E) {
    __shared__ int s_is64;
    if (threadIdx.x == 0) {
        const unsigned int* w = (const unsigned int*)raw;
        unsigned int acc = 0;
        #pragma unroll 8
        for (int i = 0; i < 128; ++i) acc |= w[2 * i + 1];
        s_is64 = (acc == 0u);
    }
    __syncthreads();
    const int is64 = s_is64;
    int i = blockIdx.x * blockDim.x + threadIdx.x;
    if (i >= 2 * E) return;
    int v;
    if (is64) v = (int)((const long long*)raw)[i];
    else      v = ((const int*)raw)[i];
    if (i < E) st[i] = v; else en[i - E] = v;
}

// 0:ne_W1(k<16) 1:ne_W2  2-3:ee_W1(a,b) 4:ee_W2  5-6:nn_W1 7:nn_W2
// 8-10:en_W1(a,b,c) 11:en_W2  12-14:pe_W1(a,b,c)
__global__ void pack_w_kernel(const float* neW1, const float* neW2,
                              const float* eeW1, const float* eeW2,
                              const float* nnW1, const float* nnW2,
                              const float* enW1, const float* enW2,
                              const float* peW1,
                              __nv_bfloat16* gh, __nv_bfloat16* gl) {
    int t = blockIdx.x * blockDim.x + threadIdx.x;
    if (t >= 15 * 16384) return;
    int chunk = t >> 14;
    int e = t & 16383;
    int k = e & 127;
    int n = e >> 7;
    const float* W; int koff = 0; int kvalid = 128;
    switch (chunk) {
        case 0:  W = neW1; kvalid = 16; break;
        case 1:  W = neW2; break;
        case 2: case 3:  W = eeW1; koff = (chunk - 2) * 128; break;
        case 4:  W = eeW2; break;
        case 5: case 6:  W = nnW1; koff = (chunk - 5) * 128; break;
        case 7:  W = nnW2; break;
        case 8: case 9: case 10: W = enW1; koff = (chunk - 8) * 128; break;
        case 11: W = enW2; break;
        default: W = peW1; koff = (chunk - 12) * 128; break;
    }
    float x = (k < kvalid) ? W[(size_t)(koff + k) * 128 + n] : 0.f;
    __nv_bfloat16 h = __float2bfloat16(x);
    __nv_bfloat16 l = __float2bfloat16(x - __bfloat162float(h));
    gh[(size_t)chunk * 16384 + n * 128 + k] = h;
    gl[(size_t)chunk * 16384 + n * 128 + k] = l;
}

// ---------------------------------------------------------------------------
// Fused node kernel (unchanged from R10).
// ---------------------------------------------------------------------------
template <int NCH, int KS1, bool PRE2, bool POST2, bool RES>
__global__ void __launch_bounds__(256, 3)
node_fused(const float* __restrict__ s0, const float* __restrict__ s1,
           int wqa, int wqb, float* __restrict__ Qa, float* __restrict__ Qb,
           int w1c0, int w2c,
           int wra, int wrb, float* __restrict__ Ra, float* __restrict__ Rb,
           const float* __restrict__ b1, const float* __restrict__ b2,
           const float* __restrict__ res, float* __restrict__ out,
           float* __restrict__ zrow, int nrows) {
    extern __shared__ char smem[];
    const uint32_t sb = smem_u32(smem);
    const int tid = threadIdx.x, lane = tid & 31, wid = tid >> 5;
    const int row0 = blockIdx.x * 64;
    const int g = lane >> 2, tig = lane & 3;
    const int m0 = (wid >> 1) * 16;
    const int nwn = (wid & 1) * 32;
    const int a_ro = (lane & 7) + ((lane >> 3) & 1) * 8;
    const int a_co = ((lane >> 4) & 1) * 8;
    const int b_ro = (lane & 7) + ((lane >> 4) & 1) * 8;
    const int b_co = ((lane >> 3) & 1) * 8;

    float* b1s = (float*)(smem + SM_B1);
    float* b2s = (float*)(smem + SM_B2);
    if (tid < 128) { b1s[tid] = b1[tid]; b2s[tid] = b2[tid]; }

    copyw_half(sb, tid, PRE2 ? wqa : w1c0, 0);

    if (zrow != nullptr) {
        float4* zp = (float4*)(zrow + (size_t)row0 * DD);
        int nz = (nrows - row0 < 64 ? nrows - row0 : 64) * 32;
        for (int i = tid; i < nz; i += 256)
            zp[i] = make_float4(0.f, 0.f, 0.f, 0.f);
    }

    stage_a<KS1 * 16>(smem, wid, lane, row0, s0, nrows);

    float acc[2][4][4];

    if constexpr (PRE2) {
        zacc2(acc);
        layer_gemm_issued<KS1>(sb, tid, wqa, m0, nwn, a_ro, a_co, b_ro, b_co, acc);
        __syncthreads();
        copyw_half(sb, tid, wqb, 0);
        acc_store(Qa, acc, row0, m0, nwn, g, tig, nrows);
        zacc2(acc);
        layer_gemm_issued<KS1>(sb, tid, wqb, m0, nwn, a_ro, a_co, b_ro, b_co, acc);
        __syncthreads();
        copyw_half(sb, tid, w1c0, 0);
        acc_store(Qb, acc, row0, m0, nwn, g, tig, nrows);
    }

    zacc2(acc);
    layer_gemm_issued<KS1>(sb, tid, w1c0, m0, nwn, a_ro, a_co, b_ro, b_co, acc);

    if constexpr (NCH == 2) {
        __syncthreads();
        copyw_half(sb, tid, w1c0 + 1, 0);
        stage_a<128>(smem, wid, lane, row0, s1, nrows);
        layer_gemm_issued<8>(sb, tid, w1c0 + 1, m0, nwn, a_ro, a_co, b_ro, b_co, acc);
    }

    __syncthreads();
    copyw_half(sb, tid, w2c, 0);
    acc_to_A(smem, acc, m0, nwn, g, tig, b1s, true);

    zacc2(acc);
    layer_gemm_issued<8>(sb, tid, w2c, m0, nwn, a_ro, a_co, b_ro, b_co, acc);

    {
        const int rl = m0 + g;
        #pragma unroll
        for (int half = 0; half < 2; ++half) {
            int grow = row0 + rl + half * 8;
            #pragma unroll
            for (int p = 0; p < 2; ++p)
                #pragma unroll
                for (int na = 0; na < 4; ++na) {
                    int cc = p * 64 + nwn + na * 8 + 2 * tig;
                    float bx = b2s[cc], by = b2s[cc + 1];
                    float rx = 0.f, ry = 0.f;
                    if (RES && grow < nrows) {
                        float2 rv = *(const float2*)(res + (size_t)grow * DD + cc);
                        rx = rv.x; ry = rv.y;
                    }
                    acc[p][na][half * 2 + 0] += bx + rx;
                    acc[p][na][half * 2 + 1] += by + ry;
                }
        }
    }

    if constexpr (POST2) {
        __syncthreads();
        copyw_half(sb, tid, wra, 0);
        acc_store(out, acc, row0, m0, nwn, g, tig, nrows);
        acc_to_A(smem, acc, m0, nwn, g, tig, nullptr, false);
        zacc2(acc);
        layer_gemm_issued<8>(sb, tid, wra, m0, nwn, a_ro, a_co, b_ro, b_co, acc);
        __syncthreads();
        copyw_half(sb, tid, wrb, 0);
        acc_store(Ra, acc, row0, m0, nwn, g, tig, nrows);
        zacc2(acc);
        layer_gemm_issued<8>(sb, tid, wrb, m0, nwn, a_ro, a_co, b_ro, b_co, acc);
        acc_store(Rb, acc, row0, m0, nwn, g, tig, nrows);
    } else {
        acc_store(out, acc, row0, m0, nwn, g, tig, nrows);
    }
}

// ---------------------------------------------------------------------------
// Edge kernel.  64 edges/CTA, 256 thr, warp tile 16x32.
// Gathers staged through smem (SM_PST overlay on B tiles).
// ---------------------------------------------------------------------------
template <int NCH, bool SCATTER, bool RES>
__global__ void __launch_bounds__(256, 3)
edge_mlp(const float* __restrict__ s0,
         const int* __restrict__ ip0, const int* __restrict__ ip1,
         const float* __restrict__ Pa, const float* __restrict__ Pb,
         int w1c, int w2c,
         const float* __restrict__ b1, const float* __restrict__ b2,
         const float* __restrict__ res, float* __restrict__ out,
         float* __restrict__ msgout, int nrows) {
    extern __shared__ char smem[];
    const uint32_t sb = smem_u32(smem);
    const int tid = threadIdx.x, lane = tid & 31, wid = tid >> 5;
    const int row0 = blockIdx.x * 64;
    const int g = lane >> 2, tig = lane & 3;
    const int m0 = (wid >> 1) * 16;
    const int nwn = (wid & 1) * 32;
    const int a_ro = (lane & 7) + ((lane >> 3) & 1) * 8;
    const int a_co = ((lane >> 4) & 1) * 8;
    const int b_ro = (lane & 7) + ((lane >> 4) & 1) * 8;
    const int b_co = ((lane >> 3) & 1) * 8;

    float* b1s = (float*)(smem + SM_B1);
    float* b2s = (float*)(smem + SM_B2);
    int*   s_ia = (int*)(smem + SM_IA);
    int*   s_ib = (int*)(smem + SM_IB);

    if (NCH == 1) copyw_half(sb, tid, w1c, 0);   // B free at start only for NCH==1

    if (tid < 128) { b1s[tid] = b1[tid]; b2s[tid] = b2[tid]; }
    if (tid < 64) {
        int grow = row0 + tid;
        int ia = 0, ib = 0;
        if (grow < nrows) { ia = ip0[grow]; ib = ip1[grow]; }
        s_ia[tid] = ia; s_ib[tid] = ib;
        const char* pa = (const char*)(Pa + (size_t)ia * DD);
        const char* pb = (const char*)(Pb + (size_t)ib * DD);
        #pragma unroll
        for (int l = 0; l < 4; ++l) {
            asm volatile("prefetch.global.L2 [%0];" :: "l"(pa + l * 128));
            asm volatile("prefetch.global.L2 [%0];" :: "l"(pb + l * 128));
        }
    }

    float acc[2][4][4];
    zacc2(acc);

    if constexpr (NCH == 1) {
        stage_a<128>(smem, wid, lane, row0, s0, nrows);
        layer_gemm_issued<8>(sb, tid, w1c, m0, nwn, a_ro, a_co, b_ro, b_co, acc);
    }

    // staged gather: P = Pa[s]+Pb[e] through smem (B region free now)
    __syncthreads();                 // B reads done (or indices visible)
    stage_p(smem, Pa, Pb, s_ia, s_ib, wid, lane);
    __syncthreads();
    pre_add_s(smem, acc, m0, nwn, g, tig);
    __syncthreads();                 // P reads done before W2 copy

    copyw_half(sb, tid, w2c, 0);
    acc_to_A(smem, acc, m0, nwn, g, tig, b1s, true);
    zacc2(acc);
    layer_gemm_issued<8>(sb, tid, w2c, m0, nwn, a_ro, a_co, b_ro, b_co, acc);

    // epilogue (R10 style)
    if constexpr (!SCATTER) {
        const int rl = m0 + g;
        #pragma unroll
        for (int half = 0; half < 2; ++half) {
            int rloc = rl + half * 8;
            int grow = row0 + rloc;
            if (grow < nrows) {
                #pragma unroll
                for (int p = 0; p < 2; ++p)
                    #pragma unroll
                    for (int na = 0; na < 4; ++na) {
                        int cc = p * 64 + nwn + na * 8 + 2 * tig;
                        float ox = acc[p][na][half * 2 + 0] + b2s[cc];
                        float oy = acc[p][na][half * 2 + 1] + b2s[cc + 1];
                        if (RES) {
                            float2 rv = *(const float2*)(res + (size_t)grow * DD + cc);
                            ox += rv.x; oy += rv.y;
                        }
                        *(float2*)(out + (size_t)grow * DD + cc) = make_float2(ox, oy);
                    }
            }
        }
    } else {
        __syncthreads();      // all warps done reading A/B tiles
        float* stg = (float*)(smem + SM_STG);
        const int rl = m0 + g;
        #pragma unroll
        for (int half = 0; half < 2; ++half) {
            int rloc = rl + half * 8;
            int grow = row0 + rloc;
            if (grow < nrows) {
                #pragma unroll
                for (int p = 0; p < 2; ++p)
                    #pragma unroll
                    for (int na = 0; na < 4; ++na) {
                        int cc = p * 64 + nwn + na * 8 + 2 * tig;
                        float ox = acc[p][na][half * 2 + 0] + b2s[cc];
                        float oy = acc[p][na][half * 2 + 1] + b2s[cc + 1];
                        if (RES) {
                            float2 rv = *(const float2*)(res + (size_t)grow * DD + cc);
                            ox += rv.x; oy += rv.y;
                        }
                        float2 o = make_float2(ox, oy);
                        *(float2*)(out + (size_t)grow * DD + cc) = o;
                        *(float2*)(stg + rloc * DD + cc) = o;
                    }
            }
        }
        __syncthreads();
        asm volatile("fence.proxy.async.shared::cta;" ::: "memory");
        if (tid < 64 && row0 + tid < nrows) {
            uint32_t src = sb + SM_STG + tid * 512;
            float* dst = msgout + (size_t)s_ib[tid] * DD;
            asm volatile(
                "cp.reduce.async.bulk.global.shared::cta.bulk_group.add.f32 "
                "[%0], [%1], 512;"
                :: "l"(dst), "r"(src) : "memory");
        }
        asm volatile("cp.async.bulk.commit_group;" ::: "memory");
        asm volatile("cp.async.bulk.wait_group 0;" ::: "memory");
    }
}

// ---------------------------------------------------------------------------
// Fused final edge kernel with staged gathers: e_new in registers, then pe.
// ---------------------------------------------------------------------------
__global__ void __launch_bounds__(256, 3)
edge_en_pe(const float* __restrict__ e,
           const int* __restrict__ ip0, const int* __restrict__ ip1,
           const float* __restrict__ Qa, const float* __restrict__ Qb,
           const float* __restrict__ Ra, const float* __restrict__ Rb,
           const float* __restrict__ en_b1, const float* __restrict__ en_b2,
           const float* __restrict__ pe_b1v, const float* __restrict__ pe_b2v,
           const float* __restrict__ pe_w2v,
           float* __restrict__ pred, int nrows) {
    extern __shared__ char smem[];
    const uint32_t sb = smem_u32(smem);
    const int tid = threadIdx.x, lane = tid & 31, wid = tid >> 5;
    const int row0 = blockIdx.x * 64;
    const int g = lane >> 2, tig = lane & 3;
    const int m0 = (wid >> 1) * 16;
    const int nwn = (wid & 1) * 32;
    const int a_ro = (lane & 7) + ((lane >> 3) & 1) * 8;
    const int a_co = ((lane >> 4) & 1) * 8;
    const int b_ro = (lane & 7) + ((lane >> 4) & 1) * 8;
    const int b_co = ((lane >> 3) & 1) * 8;

    float* b1s = (float*)(smem + SM_B1);
    float* b2s = (float*)(smem + SM_B2);
    float* b1p = (float*)(smem + SM_B1P);
    float* w2s = (float*)(smem + SM_W2V);
    int*   s_ia = (int*)(smem + SM_IA);
    int*   s_ib = (int*)(smem + SM_IB);

    copyw_half(sb, tid, 10, 0);

    if (tid < 128) {
        b1s[tid] = en_b1[tid];
        b2s[tid] = en_b2[tid];
        b1p[tid] = pe_b1v[tid];
        w2s[tid] = pe_w2v[tid];
    }
    if (tid < 64) {
        int grow = row0 + tid;
        int ia = 0, ib = 0;
        if (grow < nrows) { ia = ip0[grow]; ib = ip1[grow]; }
        s_ia[tid] = ia; s_ib[tid] = ib;
        const char* qa = (const char*)(Qa + (size_t)ia * DD);
        const char* qb = (const char*)(Qb + (size_t)ib * DD);
        const char* ra = (const char*)(Ra + (size_t)ia * DD);
        const char* rb = (const char*)(Rb + (size_t)ib * DD);
        #pragma unroll
        for (int l = 0; l < 4; ++l) {
            asm volatile("prefetch.global.L2 [%0];" :: "l"(qa + l * 128));
            asm volatile("prefetch.global.L2 [%0];" :: "l"(qb + l * 128));
            asm volatile("prefetch.global.L2 [%0];" :: "l"(ra + l * 128));
            asm volatile("prefetch.global.L2 [%0];" :: "l"(rb + l * 128));
        }
    }

    float acc[2][4][4];
    zacc2(acc);

    // ---- en layer 1: e @ enW1c + Qa[s] + Qb[e] (staged gather) ----
    stage_a<128>(smem, wid, lane, row0, e, nrows);
    layer_gemm_issued<8>(sb, tid, 10, m0, nwn, a_ro, a_co, b_ro, b_co, acc);
    __syncthreads();                 // B reads done
    stage_p(smem, Qa, Qb, s_ia, s_ib, wid, lane);
    __syncthreads();
    pre_add_s(smem, acc, m0, nwn, g, tig);
    __syncthreads();                 // P reads done before W copy

    // ---- en layer 2 ----
    copyw_half(sb, tid, 11, 0);
    acc_to_A(smem, acc, m0, nwn, g, tig, b1s, true);
    zacc2(acc);
    layer_gemm_issued<8>(sb, tid, 11, m0, nwn, a_ro, a_co, b_ro, b_co, acc);

    // fold en_b2 + residual e  ->  e_new stays in registers
    {
        const int rl = m0 + g;
        #pragma unroll
        for (int half = 0; half < 2; ++half) {
            int grow = row0 + rl + half * 8;
            if (grow < nrows) {
                #pragma unroll
                for (int p = 0; p < 2; ++p)
                    #pragma unroll
                    for (int na = 0; na < 4; ++na) {
                        int cc = p * 64 + nwn + na * 8 + 2 * tig;
                        float2 rv = *(const float2*)(e + (size_t)grow * DD + cc);
                        acc[p][na][half * 2 + 0] += b2s[cc] + rv.x;
                        acc[p][na][half * 2 + 1] += b2s[cc + 1] + rv.y;
                    }
            }
        }
    }

    // ---- pe layer 1: e_new @ peW1c + Ra[s] + Rb[e] (staged gather) ----
    __syncthreads();
    copyw_half(sb, tid, 14, 0);
    acc_to_A(smem, acc, m0, nwn, g, tig, nullptr, false);
    zacc2(acc);
    layer_gemm_issued<8>(sb, tid, 14, m0, nwn, a_ro, a_co, b_ro, b_co, acc);
    __syncthreads();                 // B reads done
    stage_p(smem, Ra, Rb, s_ia, s_ib, wid, lane);
    __syncthreads();
    pre_add_s(smem, acc, m0, nwn, g, tig);

    // ---- pe layer 2: per-row dot ----
    float* hT = (float*)(smem + SM_AH);
    __syncthreads();                 // A/P reads done before overwrite
    {
        const int rl = m0 + g;
        #pragma unroll
        for (int p = 0; p < 2; ++p)
            #pragma unroll
            for (int na = 0; na < 4; ++na) {
                int cc = p * 64 + nwn + na * 8 + 2 * tig;
                hT[rl * 129 + cc]           = fmaxf(acc[p][na][0] + b1p[cc], 0.f);
                hT[rl * 129 + cc + 1]       = fmaxf(acc[p][na][1] + b1p[cc + 1], 0.f);
                hT[(rl + 8) * 129 + cc]     = fmaxf(acc[p][na][2] + b1p[cc], 0.f);
                hT[(rl + 8) * 129 + cc + 1] = fmaxf(acc[p][na][3] + b1p[cc + 1], 0.f);
            }
    }
    __syncthreads();
    if (tid < 64) {
        int grow = row0 + tid;
        float a = __ldg(&pe_b2v[0]);
        #pragma unroll 8
        for (int k = 0; k < 128; ++k) a += hT[tid * 129 + k] * w2s[k];
        if (grow < nrows) pred[grow] = a;
    }
}

// ---------------------------------------------------------------------------
extern "C" void kernel_launch(void* const* d_in, const int* in_sizes, int n_in,
                              void* d_out, int out_size) {
    const float* nodes = (const float*)d_in[0];
    const void*  eidx  = d_in[1];
    const float* ne_W1 = (const float*)d_in[2];
    const float* ne_b1 = (const float*)d_in[3];
    const float* ne_W2 = (const float*)d_in[4];
    const float* ne_b2 = (const float*)d_in[5];
    const float* ee_W1 = (const float*)d_in[6];
    const float* ee_b1 = (const float*)d_in[7];
    const float* ee_W2 = (const float*)d_in[8];
    const float* ee_b2 = (const float*)d_in[9];
    const float* nn_W1 = (const float*)d_in[10];
    const float* nn_b1 = (const float*)d_in[11];
    const float* nn_W2 = (const float*)d_in[12];
    const float* nn_b2 = (const float*)d_in[13];
    const float* en_W1 = (const float*)d_in[14];
    const float* en_b1 = (const float*)d_in[15];
    const float* en_W2 = (const float*)d_in[16];
    const float* en_b2 = (const float*)d_in[17];
    const float* pe_W1 = (const float*)d_in[18];
    const float* pe_b1 = (const float*)d_in[19];
    const float* pe_W2 = (const float*)d_in[20];
    const float* pe_b2 = (const float*)d_in[21];

    float *h, *h2, *m0, *m1, *e, *pa, *pb, *pc, *pd;
    int *st, *en_;
    __nv_bfloat16 *pwh, *pwl;
    cudaGetSymbolAddress((void**)&h,   g_h);
    cudaGetSymbolAddress((void**)&h2,  g_h2);
    cudaGetSymbolAddress((void**)&m0,  g_m0);
    cudaGetSymbolAddress((void**)&m1,  g_m1);
    cudaGetSymbolAddress((void**)&e,   g_e);
    cudaGetSymbolAddress((void**)&pa,  g_pa);
    cudaGetSymbolAddress((void**)&pb,  g_pb);
    cudaGetSymbolAddress((void**)&pc,  g_pc);
    cudaGetSymbolAddress((void**)&pd,  g_pd);
    cudaGetSymbolAddress((void**)&st,  g_start);
    cudaGetSymbolAddress((void**)&en_, g_end);
    cudaGetSymbolAddress((void**)&pwh, g_pwh);
    cudaGetSymbolAddress((void**)&pwl, g_pwl);

    cudaFuncSetAttribute(node_fused<1, 1, false, true, false>,
                         cudaFuncAttributeMaxDynamicSharedMemorySize, SM_TOTAL);
    cudaFuncSetAttribute(node_fused<2, 8, true, false, true>,
                         cudaFuncAttributeMaxDynamicSharedMemorySize, SM_TOTAL);
    cudaFuncSetAttribute(node_fused<2, 8, true, true, true>,
                         cudaFuncAttributeMaxDynamicSharedMemorySize, SM_TOTAL);
    cudaFuncSetAttribute(edge_mlp<0, true, false>,
                         cudaFuncAttributeMaxDynamicSharedMemorySize, SM_TOTAL);
    cudaFuncSetAttribute(edge_mlp<1, true, true>,
                         cudaFuncAttributeMaxDynamicSharedMemorySize, SM_TOTAL);
    cudaFuncSetAttribute(edge_en_pe,
                         cudaFuncAttributeMaxDynamicSharedMemorySize, SM_TOTAL);

    const int nblk_n = (N_NODES + 63) / 64;  // 1563
    const int nblk_e = (N_EDGES + 63) / 64;  // 9375

    convert_idx_kernel<<<(2 * N_EDGES + 255) / 256, 256>>>(eidx, st, en_, N_EDGES);
    pack_w_kernel<<<(15 * 16384 + 255) / 256, 256>>>(
        ne_W1, ne_W2, ee_W1, ee_W2, nn_W1, nn_W2, en_W1, en_W2, pe_W1, pwh, pwl);

    // h = MLP_ne(nodes);  Pa = h@eeW1a, Pb = h@eeW1b;  zero m0
    node_fused<1, 1, false, true, false><<<nblk_n, 256, SM_TOTAL>>>(
        nodes, nullptr, 0, 0, nullptr, nullptr, 0, 1,
        2, 3, pa, pb, ne_b1, ne_b2, nullptr, h, m0, N_NODES);

    // e = relu(Pa[s]+Pb[e]+b1)@eeW2 + b2;  scatter e -> m0
    edge_mlp<0, true, false><<<nblk_e, 256, SM_TOTAL>>>(
        nullptr, st, en_, pa, pb, 0, 4,
        ee_b1, ee_b2, nullptr, e, m0, N_EDGES);

    float* hA = h;
    float* hB = h2;
    float* msgs[2] = {m0, m1};

    for (int it = 0; it < NUM_ITERS; ++it) {
        float* mcur = msgs[it & 1];
        float* mnxt = msgs[(it + 1) & 1];
        const bool last = (it == NUM_ITERS - 1);
        float* zr = last ? nullptr : mnxt;

        if (!last) {
            node_fused<2, 8, true, false, true><<<nblk_n, 256, SM_TOTAL>>>(
                hA, mcur, 8, 9, pa, pb, 5, 7,
                0, 0, nullptr, nullptr, nn_b1, nn_b2, hA, hB, zr, N_NODES);

            edge_mlp<1, true, true><<<nblk_e, 256, SM_TOTAL>>>(
                e, st, en_, pa, pb, 10, 11,
                en_b1, en_b2, e, e, mnxt, N_EDGES);
        } else {
            node_fused<2, 8, true, true, true><<<nblk_n, 256, SM_TOTAL>>>(
                hA, mcur, 8, 9, pa, pb, 5, 7,
                12, 13, pc, pd, nn_b1, nn_b2, hA, hB, zr, N_NODES);

            edge_en_pe<<<nblk_e, 256, SM_TOTAL>>>(
                e, st, en_, pa, pb, pc, pd,
                en_b1, en_b2, pe_b1, pe_b2, pe_W2,
                (float*)d_out, N_EDGES);
        }

        float* t = hA; hA = hB; hB = t;
    }
}

// round 15
// speedup vs baseline: 1.0626x; 1.0150x over previous
#include <cuda_runtime.h>
#include <cuda_bf16.h>
#include <cstdint>

// ---------------------------------------------------------------------------
// InteractionGNN on GB300 — round 15: R14 base (best, 3596us) + smem-staged
// residual reads in en epilogues (coalesced e-row loads into padded smem
// replace scattered per-fragment LDGs; same trick that won R14 for gathers).
// GEMM core: mma.sync bf16 3-term split (Ah*Wh + Ah*Wl + Al*Wh), fp32 accum.
// ---------------------------------------------------------------------------

#define N_NODES 100000
#define N_EDGES 600000
#define DD      128
#define NUM_ITERS 4

// ---------------- device scratch -------------------------------------------
__device__ float g_h  [(size_t)N_NODES * DD];
__device__ float g_h2 [(size_t)N_NODES * DD];
__device__ float g_m0 [(size_t)N_NODES * DD];
__device__ float g_m1 [(size_t)N_NODES * DD];
__device__ float g_e  [(size_t)N_EDGES * DD];
__device__ float g_pa [(size_t)N_NODES * DD];
__device__ float g_pb [(size_t)N_NODES * DD];
__device__ float g_pc [(size_t)N_NODES * DD];
__device__ float g_pd [(size_t)N_NODES * DD];
__device__ int   g_start[N_EDGES];
__device__ int   g_end  [N_EDGES];
// prepacked weights: 15 chunks x [128 n][128 k] bf16, hi and lo images
__device__ __nv_bfloat16 g_pwh[15 * 16384];
__device__ __nv_bfloat16 g_pwl[15 * 16384];

// ---------------- smem layout ------------------------------------------------
static constexpr int ROW_B  = 272;
static constexpr int SM_B1  = 64;     // 128 f32
static constexpr int SM_W2V = 576;    // 128 f32
static constexpr int SM_B2  = 1088;   // 128 f32
static constexpr int SM_B1P = 1600;   // 128 f32 (pe_b1 in fused kernel)
static constexpr int SM_IA  = 2112;   // 64 ints
static constexpr int SM_IB  = 2368;   // 64 ints
static constexpr int SM_AH  = 2688;
static constexpr int TBUF   = 64 * ROW_B;          // 17408
static constexpr int SM_AL  = SM_AH + TBUF;        // 20096
static constexpr int SM_BH  = SM_AL + TBUF;        // 37504
static constexpr int SM_BL  = SM_BH + TBUF;        // 54912
static constexpr int SM_TOTAL = SM_BL + TBUF;      // 72320
// scatter staging: 64 rows x 512 B, overlaid on A tiles
static constexpr int SM_STG = SM_AH;
// gather/residual staging: 64 rows x 544 B (PSTR=136 floats), overlaid on B
static constexpr int SM_PST = SM_BH;               // 64*544 = 34816 = 2*TBUF
static constexpr int PSTR   = 136;                 // floats; 2-way conflicts

// ---------------- helpers -----------------------------------------------------
__device__ __forceinline__ uint32_t smem_u32(const void* p) {
    uint32_t a;
    asm("{ .reg .u64 t; cvta.to.shared.u64 t, %1; cvt.u32.u64 %0, t; }"
        : "=r"(a) : "l"(p));
    return a;
}

#define LDSM_X4(R0, R1, R2, R3, ADDR) \
    asm volatile("ldmatrix.sync.aligned.m8n8.x4.shared.b16 {%0,%1,%2,%3}, [%4];" \
                 : "=r"(R0), "=r"(R1), "=r"(R2), "=r"(R3) : "r"(ADDR))

__device__ __forceinline__ void mma16816(float* c, const uint32_t* a,
                                         const uint32_t* b) {
    asm volatile(
        "mma.sync.aligned.m16n8k16.row.col.f32.bf16.bf16.f32 "
        "{%0,%1,%2,%3}, {%4,%5,%6,%7}, {%8,%9}, {%0,%1,%2,%3};"
        : "+f"(c[0]), "+f"(c[1]), "+f"(c[2]), "+f"(c[3])
        : "r"(a[0]), "r"(a[1]), "r"(a[2]), "r"(a[3]), "r"(b[0]), "r"(b[1]));
}

__device__ __forceinline__ uint32_t pack_bf2(float a, float b) {
    __nv_bfloat162 t = __floats2bfloat162_rn(a, b);
    return *reinterpret_cast<uint32_t*>(&t);
}

__device__ __forceinline__ void split2(float x, float y, uint32_t& H, uint32_t& L) {
    __nv_bfloat16 hx = __float2bfloat16(x);
    __nv_bfloat16 hy = __float2bfloat16(y);
    float lx = x - __bfloat162float(hx);
    float ly = y - __bfloat162float(hy);
    H = pack_bf2(__bfloat162float(hx), __bfloat162float(hy));
    L = pack_bf2(lx, ly);
}

#define CP_WAIT_ALL() asm volatile("cp.async.wait_group 0;" ::: "memory")

__device__ __forceinline__ void copyw_half(uint32_t sb, int tid, int chunk,
                                           int half) {
    const char* srcH = (const char*)(g_pwh + (size_t)chunk * 16384 + half * 8192);
    const char* srcL = (const char*)(g_pwl + (size_t)chunk * 16384 + half * 8192);
    #pragma unroll
    for (int i = tid; i < 1024; i += 256) {
        int rr = i >> 4, q = i & 15;
        uint32_t d = sb + SM_BH + rr * ROW_B + q * 16;
        asm volatile("cp.async.cg.shared.global [%0], [%1], 16;"
                     :: "r"(d), "l"(srcH + i * 16));
        asm volatile("cp.async.cg.shared.global [%0], [%1], 16;"
                     :: "r"(d + (uint32_t)TBUF), "l"(srcL + i * 16));
    }
    asm volatile("cp.async.commit_group;" ::: "memory");
}

template <int KSTEPS>
__device__ __forceinline__ void gemm3h(uint32_t sb, int m0, int nloc,
                                       int a_ro, int a_co, int b_ro, int b_co,
                                       float accp[4][4]) {
    #pragma unroll
    for (int ks = 0; ks < KSTEPS; ++ks) {
        const int k0 = ks * 16;
        uint32_t ah[4], al[4];
        {
            uint32_t ro = (uint32_t)(m0 + a_ro) * ROW_B + (uint32_t)(k0 + a_co) * 2;
            LDSM_X4(ah[0], ah[1], ah[2], ah[3], sb + SM_AH + ro);
            LDSM_X4(al[0], al[1], al[2], al[3], sb + SM_AL + ro);
        }
        uint32_t bh[4][2], bl[4][2];
        #pragma unroll
        for (int nb = 0; nb < 2; ++nb) {
            uint32_t ro = (uint32_t)(nloc + nb * 16 + b_ro) * ROW_B +
                          (uint32_t)(k0 + b_co) * 2;
            uint32_t r0, r1, r2, r3;
            LDSM_X4(r0, r1, r2, r3, sb + SM_BH + ro);
            bh[nb * 2][0] = r0; bh[nb * 2][1] = r1;
            bh[nb * 2 + 1][0] = r2; bh[nb * 2 + 1][1] = r3;
            LDSM_X4(r0, r1, r2, r3, sb + SM_BL + ro);
            bl[nb * 2][0] = r0; bl[nb * 2][1] = r1;
            bl[nb * 2 + 1][0] = r2; bl[nb * 2 + 1][1] = r3;
        }
        #pragma unroll
        for (int na = 0; na < 4; ++na) {
            mma16816(accp[na], ah, bh[na]);
            mma16816(accp[na], ah, bl[na]);
            mma16816(accp[na], al, bh[na]);
        }
    }
}

template <int KS>
__device__ __forceinline__ void layer_gemm_issued(uint32_t sb, int tid, int chunk,
                                                  int m0, int nloc,
                                                  int a_ro, int a_co,
                                                  int b_ro, int b_co,
                                                  float acc[2][4][4]) {
    CP_WAIT_ALL();
    __syncthreads();
    gemm3h<KS>(sb, m0, nloc, a_ro, a_co, b_ro, b_co, acc[0]);
    __syncthreads();
    copyw_half(sb, tid, chunk, 1);
    CP_WAIT_ALL();
    __syncthreads();
    gemm3h<KS>(sb, m0, nloc, a_ro, a_co, b_ro, b_co, acc[1]);
}

__device__ __forceinline__ void zacc2(float acc[2][4][4]) {
    #pragma unroll
    for (int q = 0; q < 32; ++q) (&acc[0][0][0])[q] = 0.f;
}

template <int SRC_K>
__device__ __forceinline__ void stage_a(char* smem, int wid, int lane, int row0,
                                        const float* __restrict__ src, int nrows) {
    for (int r = wid; r < 64; r += 8) {
        int grow = row0 + r;
        float4 v = make_float4(0.f, 0.f, 0.f, 0.f);
        if (grow < nrows && lane < SRC_K / 4)
            v = ((const float4*)(src + (size_t)grow * SRC_K))[lane];
        if (lane < SRC_K / 4) {
            uint32_t h0, l0, h1, l1;
            split2(v.x, v.y, h0, l0);
            split2(v.z, v.w, h1, l1);
            uint32_t off = r * ROW_B + lane * 8;
            *(uint2*)(smem + SM_AH + off) = make_uint2(h0, h1);
            *(uint2*)(smem + SM_AL + off) = make_uint2(l0, l1);
        }
    }
}

__device__ __forceinline__ void acc_to_A(char* smem, float acc[2][4][4],
                                         int m0, int nwn, int g, int tig,
                                         const float* b1s, bool relu) {
    const int rl = m0 + g;
    #pragma unroll
    for (int p = 0; p < 2; ++p)
        #pragma unroll
        for (int na = 0; na < 4; ++na) {
            int cc = p * 64 + nwn + na * 8 + 2 * tig;
            float bx = b1s ? b1s[cc] : 0.f;
            float by = b1s ? b1s[cc + 1] : 0.f;
            float v0 = acc[p][na][0] + bx, v1 = acc[p][na][1] + by;
            float v2 = acc[p][na][2] + bx, v3 = acc[p][na][3] + by;
            if (relu) {
                v0 = fmaxf(v0, 0.f); v1 = fmaxf(v1, 0.f);
                v2 = fmaxf(v2, 0.f); v3 = fmaxf(v3, 0.f);
            }
            uint32_t H, L;
            split2(v0, v1, H, L);
            *(uint32_t*)(smem + SM_AH + rl * ROW_B + cc * 2) = H;
            *(uint32_t*)(smem + SM_AL + rl * ROW_B + cc * 2) = L;
            split2(v2, v3, H, L);
            *(uint32_t*)(smem + SM_AH + (rl + 8) * ROW_B + cc * 2) = H;
            *(uint32_t*)(smem + SM_AL + (rl + 8) * ROW_B + cc * 2) = L;
        }
}

__device__ __forceinline__ void acc_store(float* __restrict__ out,
                                          float acc[2][4][4], int row0,
                                          int m0, int nwn, int g, int tig,
                                          int nrows) {
    const int rl = m0 + g;
    const int g0 = row0 + rl, g1 = g0 + 8;
    #pragma unroll
    for (int p = 0; p < 2; ++p)
        #pragma unroll
        for (int na = 0; na < 4; ++na) {
            int cc = p * 64 + nwn + na * 8 + 2 * tig;
            if (g0 < nrows)
                *(float2*)(out + (size_t)g0 * DD + cc) =
                    make_float2(acc[p][na][0], acc[p][na][1]);
            if (g1 < nrows)
                *(float2*)(out + (size_t)g1 * DD + cc) =
                    make_float2(acc[p][na][2], acc[p][na][3]);
        }
}

// ---- smem-staged gather: P = U[ia] + V[ib] into padded smem ----------------
__device__ __forceinline__ void stage_p(char* smem,
                                        const float* __restrict__ U,
                                        const float* __restrict__ V,
                                        const int* s_ia, const int* s_ib,
                                        int wid, int lane) {
    float* stp = (float*)(smem + SM_PST);
    #pragma unroll
    for (int r = wid; r < 64; r += 8) {
        const float4 va = ((const float4*)(U + (size_t)s_ia[r] * DD))[lane];
        const float4 vb = ((const float4*)(V + (size_t)s_ib[r] * DD))[lane];
        *(float4*)(stp + r * PSTR + lane * 4) =
            make_float4(va.x + vb.x, va.y + vb.y, va.z + vb.z, va.w + vb.w);
    }
}

// coalesced stage of contiguous rows src[row0..row0+64) into padded PST
__device__ __forceinline__ void stage_rows(char* smem,
                                           const float* __restrict__ src,
                                           int row0, int wid, int lane) {
    float* stp = (float*)(smem + SM_PST);
    #pragma unroll
    for (int r = wid; r < 64; r += 8) {
        float4 v = ((const float4*)(src + (size_t)(row0 + r) * DD))[lane];
        *(float4*)(stp + r * PSTR + lane * 4) = v;
    }
}

__device__ __forceinline__ void pre_add_s(char* smem, float acc[2][4][4],
                                          int m0, int nwn, int g, int tig) {
    const float* stp = (const float*)(smem + SM_PST);
    const int rl = m0 + g;
    #pragma unroll
    for (int half = 0; half < 2; ++half) {
        const float* row = stp + (rl + half * 8) * PSTR;
        #pragma unroll
        for (int p = 0; p < 2; ++p)
            #pragma unroll
            for (int na = 0; na < 4; ++na) {
                int cc = p * 64 + nwn + na * 8 + 2 * tig;
                float2 v = *(const float2*)(row + cc);
                acc[p][na][half * 2 + 0] += v.x;
                acc[p][na][half * 2 + 1] += v.y;
            }
    }
}

// ---------------- small utility kernels ------------------------------------
__global__ void convert_idx_kernel(const void* __restrict__ raw,
                                   int* __restrict__ st, int* __restrict__ en,
                                   int E) {
    __shared__ int s_is64;
    if (threadIdx.x == 0) {
        const unsigned int* w = (const unsigned int*)raw;
        unsigned int acc = 0;
        #pragma unroll 8
        for (int i = 0; i < 128; ++i) acc |= w[2 * i + 1];
        s_is64 = (acc == 0u);
    }
    __syncthreads();
    const int is64 = s_is64;
    int i = blockIdx.x * blockDim.x + threadIdx.x;
    if (i >= 2 * E) return;
    int v;
    if (is64) v = (int)((const long long*)raw)[i];
    else      v = ((const int*)raw)[i];
    if (i < E) st[i] = v; else en[i - E] = v;
}

// 0:ne_W1(k<16) 1:ne_W2  2-3:ee_W1(a,b) 4:ee_W2  5-6:nn_W1 7:nn_W2
// 8-10:en_W1(a,b,c) 11:en_W2  12-14:pe_W1(a,b,c)
__global__ void pack_w_kernel(const float* neW1, const float* neW2,
                              const float* eeW1, const float* eeW2,
                              const float* nnW1, const float* nnW2,
                              const float* enW1, const float* enW2,
                              const float* peW1,
                              __nv_bfloat16* gh, __nv_bfloat16* gl) {
    int t = blockIdx.x * blockDim.x + threadIdx.x;
    if (t >= 15 * 16384) return;
    int chunk = t >> 14;
    int e = t & 16383;
    int k = e & 127;
    int n = e >> 7;
    const float* W; int koff = 0; int kvalid = 128;
    switch (chunk) {
        case 0:  W = neW1; kvalid = 16; break;
        case 1:  W = neW2; break;
        case 2: case 3:  W = eeW1; koff = (chunk - 2) * 128; break;
        case 4:  W = eeW2; break;
        case 5: case 6:  W = nnW1; koff = (chunk - 5) * 128; break;
        case 7:  W = nnW2; break;
        case 8: case 9: case 10: W = enW1; koff = (chunk - 8) * 128; break;
        case 11: W = enW2; break;
        default: W = peW1; koff = (chunk - 12) * 128; break;
    }
    float x = (k < kvalid) ? W[(size_t)(koff + k) * 128 + n] : 0.f;
    __nv_bfloat16 h = __float2bfloat16(x);
    __nv_bfloat16 l = __float2bfloat16(x - __bfloat162float(h));
    gh[(size_t)chunk * 16384 + n * 128 + k] = h;
    gl[(size_t)chunk * 16384 + n * 128 + k] = l;
}

// ---------------------------------------------------------------------------
// Fused node kernel (unchanged from R10/R14).
// ---------------------------------------------------------------------------
template <int NCH, int KS1, bool PRE2, bool POST2, bool RES>
__global__ void __launch_bounds__(256, 3)
node_fused(const float* __restrict__ s0, const float* __restrict__ s1,
           int wqa, int wqb, float* __restrict__ Qa, float* __restrict__ Qb,
           int w1c0, int w2c,
           int wra, int wrb, float* __restrict__ Ra, float* __restrict__ Rb,
           const float* __restrict__ b1, const float* __restrict__ b2,
           const float* __restrict__ res, float* __restrict__ out,
           float* __restrict__ zrow, int nrows) {
    extern __shared__ char smem[];
    const uint32_t sb = smem_u32(smem);
    const int tid = threadIdx.x, lane = tid & 31, wid = tid >> 5;
    const int row0 = blockIdx.x * 64;
    const int g = lane >> 2, tig = lane & 3;
    const int m0 = (wid >> 1) * 16;
    const int nwn = (wid & 1) * 32;
    const int a_ro = (lane & 7) + ((lane >> 3) & 1) * 8;
    const int a_co = ((lane >> 4) & 1) * 8;
    const int b_ro = (lane & 7) + ((lane >> 4) & 1) * 8;
    const int b_co = ((lane >> 3) & 1) * 8;

    float* b1s = (float*)(smem + SM_B1);
    float* b2s = (float*)(smem + SM_B2);
    if (tid < 128) { b1s[tid] = b1[tid]; b2s[tid] = b2[tid]; }

    copyw_half(sb, tid, PRE2 ? wqa : w1c0, 0);

    if (zrow != nullptr) {
        float4* zp = (float4*)(zrow + (size_t)row0 * DD);
        int nz = (nrows - row0 < 64 ? nrows - row0 : 64) * 32;
        for (int i = tid; i < nz; i += 256)
            zp[i] = make_float4(0.f, 0.f, 0.f, 0.f);
    }

    stage_a<KS1 * 16>(smem, wid, lane, row0, s0, nrows);

    float acc[2][4][4];

    if constexpr (PRE2) {
        zacc2(acc);
        layer_gemm_issued<KS1>(sb, tid, wqa, m0, nwn, a_ro, a_co, b_ro, b_co, acc);
        __syncthreads();
        copyw_half(sb, tid, wqb, 0);
        acc_store(Qa, acc, row0, m0, nwn, g, tig, nrows);
        zacc2(acc);
        layer_gemm_issued<KS1>(sb, tid, wqb, m0, nwn, a_ro, a_co, b_ro, b_co, acc);
        __syncthreads();
        copyw_half(sb, tid, w1c0, 0);
        acc_store(Qb, acc, row0, m0, nwn, g, tig, nrows);
    }

    zacc2(acc);
    layer_gemm_issued<KS1>(sb, tid, w1c0, m0, nwn, a_ro, a_co, b_ro, b_co, acc);

    if constexpr (NCH == 2) {
        __syncthreads();
        copyw_half(sb, tid, w1c0 + 1, 0);
        stage_a<128>(smem, wid, lane, row0, s1, nrows);
        layer_gemm_issued<8>(sb, tid, w1c0 + 1, m0, nwn, a_ro, a_co, b_ro, b_co, acc);
    }

    __syncthreads();
    copyw_half(sb, tid, w2c, 0);
    acc_to_A(smem, acc, m0, nwn, g, tig, b1s, true);

    zacc2(acc);
    layer_gemm_issued<8>(sb, tid, w2c, m0, nwn, a_ro, a_co, b_ro, b_co, acc);

    {
        const int rl = m0 + g;
        #pragma unroll
        for (int half = 0; half < 2; ++half) {
            int grow = row0 + rl + half * 8;
            #pragma unroll
            for (int p = 0; p < 2; ++p)
                #pragma unroll
                for (int na = 0; na < 4; ++na) {
                    int cc = p * 64 + nwn + na * 8 + 2 * tig;
                    float bx = b2s[cc], by = b2s[cc + 1];
                    float rx = 0.f, ry = 0.f;
                    if (RES && grow < nrows) {
                        float2 rv = *(const float2*)(res + (size_t)grow * DD + cc);
                        rx = rv.x; ry = rv.y;
                    }
                    acc[p][na][half * 2 + 0] += bx + rx;
                    acc[p][na][half * 2 + 1] += by + ry;
                }
        }
    }

    if constexpr (POST2) {
        __syncthreads();
        copyw_half(sb, tid, wra, 0);
        acc_store(out, acc, row0, m0, nwn, g, tig, nrows);
        acc_to_A(smem, acc, m0, nwn, g, tig, nullptr, false);
        zacc2(acc);
        layer_gemm_issued<8>(sb, tid, wra, m0, nwn, a_ro, a_co, b_ro, b_co, acc);
        __syncthreads();
        copyw_half(sb, tid, wrb, 0);
        acc_store(Ra, acc, row0, m0, nwn, g, tig, nrows);
        zacc2(acc);
        layer_gemm_issued<8>(sb, tid, wrb, m0, nwn, a_ro, a_co, b_ro, b_co, acc);
        acc_store(Rb, acc, row0, m0, nwn, g, tig, nrows);
    } else {
        acc_store(out, acc, row0, m0, nwn, g, tig, nrows);
    }
}

// ---------------------------------------------------------------------------
// Edge kernel.  64 edges/CTA, 256 thr, warp tile 16x32.
// Gathers AND residual reads staged through padded smem.
// ---------------------------------------------------------------------------
template <int NCH, bool SCATTER, bool RES>
__global__ void __launch_bounds__(256, 3)
edge_mlp(const float* __restrict__ s0,
         const int* __restrict__ ip0, const int* __restrict__ ip1,
         const float* __restrict__ Pa, const float* __restrict__ Pb,
         int w1c, int w2c,
         const float* __restrict__ b1, const float* __restrict__ b2,
         const float* __restrict__ res, float* __restrict__ out,
         float* __restrict__ msgout, int nrows) {
    extern __shared__ char smem[];
    const uint32_t sb = smem_u32(smem);
    const int tid = threadIdx.x, lane = tid & 31, wid = tid >> 5;
    const int row0 = blockIdx.x * 64;
    const int g = lane >> 2, tig = lane & 3;
    const int m0 = (wid >> 1) * 16;
    const int nwn = (wid & 1) * 32;
    const int a_ro = (lane & 7) + ((lane >> 3) & 1) * 8;
    const int a_co = ((lane >> 4) & 1) * 8;
    const int b_ro = (lane & 7) + ((lane >> 4) & 1) * 8;
    const int b_co = ((lane >> 3) & 1) * 8;

    float* b1s = (float*)(smem + SM_B1);
    float* b2s = (float*)(smem + SM_B2);
    int*   s_ia = (int*)(smem + SM_IA);
    int*   s_ib = (int*)(smem + SM_IB);

    if (NCH == 1) copyw_half(sb, tid, w1c, 0);

    if (tid < 128) { b1s[tid] = b1[tid]; b2s[tid] = b2[tid]; }
    if (tid < 64) {
        int grow = row0 + tid;
        int ia = 0, ib = 0;
        if (grow < nrows) { ia = ip0[grow]; ib = ip1[grow]; }
        s_ia[tid] = ia; s_ib[tid] = ib;
        const char* pa = (const char*)(Pa + (size_t)ia * DD);
        const char* pb = (const char*)(Pb + (size_t)ib * DD);
        #pragma unroll
        for (int l = 0; l < 4; ++l) {
            asm volatile("prefetch.global.L2 [%0];" :: "l"(pa + l * 128));
            asm volatile("prefetch.global.L2 [%0];" :: "l"(pb + l * 128));
        }
    }

    float acc[2][4][4];
    zacc2(acc);

    if constexpr (NCH == 1) {
        stage_a<128>(smem, wid, lane, row0, s0, nrows);
        layer_gemm_issued<8>(sb, tid, w1c, m0, nwn, a_ro, a_co, b_ro, b_co, acc);
    }

    // staged gather: P = Pa[s]+Pb[e] through padded smem
    __syncthreads();                 // B reads done (or indices visible)
    stage_p(smem, Pa, Pb, s_ia, s_ib, wid, lane);
    __syncthreads();
    pre_add_s(smem, acc, m0, nwn, g, tig);
    __syncthreads();                 // P reads done before W2 copy

    copyw_half(sb, tid, w2c, 0);
    acc_to_A(smem, acc, m0, nwn, g, tig, b1s, true);
    zacc2(acc);
    layer_gemm_issued<8>(sb, tid, w2c, m0, nwn, a_ro, a_co, b_ro, b_co, acc);

    // epilogue
    if constexpr (!SCATTER) {
        const int rl = m0 + g;
        #pragma unroll
        for (int half = 0; half < 2; ++half) {
            int rloc = rl + half * 8;
            int grow = row0 + rloc;
            if (grow < nrows) {
                #pragma unroll
                for (int p = 0; p < 2; ++p)
                    #pragma unroll
                    for (int na = 0; na < 4; ++na) {
                        int cc = p * 64 + nwn + na * 8 + 2 * tig;
                        float ox = acc[p][na][half * 2 + 0] + b2s[cc];
                        float oy = acc[p][na][half * 2 + 1] + b2s[cc + 1];
                        if (RES) {
                            float2 rv = *(const float2*)(res + (size_t)grow * DD + cc);
                            ox += rv.x; oy += rv.y;
                        }
                        *(float2*)(out + (size_t)grow * DD + cc) = make_float2(ox, oy);
                    }
            }
        }
    } else {
        __syncthreads();      // all warps done reading A/B tiles
        // residual: coalesced stage into padded PST (B region free post-GEMM)
        if (RES) {
            stage_rows(smem, res, row0, wid, lane);
            __syncthreads();
        }
        float* stg = (float*)(smem + SM_STG);
        const float* rst = (const float*)(smem + SM_PST);
        const int rl = m0 + g;
        #pragma unroll
        for (int half = 0; half < 2; ++half) {
            int rloc = rl + half * 8;
            int grow = row0 + rloc;
            if (grow < nrows) {
                const float* rrow = rst + rloc * PSTR;
                #pragma unroll
                for (int p = 0; p < 2; ++p)
                    #pragma unroll
                    for (int na = 0; na < 4; ++na) {
                        int cc = p * 64 + nwn + na * 8 + 2 * tig;
                        float ox = acc[p][na][half * 2 + 0] + b2s[cc];
                        float oy = acc[p][na][half * 2 + 1] + b2s[cc + 1];
                        if (RES) {
                            float2 rv = *(const float2*)(rrow + cc);
                            ox += rv.x; oy += rv.y;
                        }
                        float2 o = make_float2(ox, oy);
                        *(float2*)(out + (size_t)grow * DD + cc) = o;
                        *(float2*)(stg + rloc * DD + cc) = o;
                    }
            }
        }
        __syncthreads();
        asm volatile("fence.proxy.async.shared::cta;" ::: "memory");
        if (tid < 64 && row0 + tid < nrows) {
            uint32_t src = sb + SM_STG + tid * 512;
            float* dst = msgout + (size_t)s_ib[tid] * DD;
            asm volatile(
                "cp.reduce.async.bulk.global.shared::cta.bulk_group.add.f32 "
                "[%0], [%1], 512;"
                :: "l"(dst), "r"(src) : "memory");
        }
        asm volatile("cp.async.bulk.commit_group;" ::: "memory");
        asm volatile("cp.async.bulk.wait_group 0;" ::: "memory");
    }
}

// ---------------------------------------------------------------------------
// Fused final edge kernel with staged gathers + staged residual.
// ---------------------------------------------------------------------------
__global__ void __launch_bounds__(256, 3)
edge_en_pe(const float* __restrict__ e,
           const int* __restrict__ ip0, const int* __restrict__ ip1,
           const float* __restrict__ Qa, const float* __restrict__ Qb,
           const float* __restrict__ Ra, const float* __restrict__ Rb,
           const float* __restrict__ en_b1, const float* __restrict__ en_b2,
           const float* __restrict__ pe_b1v, const float* __restrict__ pe_b2v,
           const float* __restrict__ pe_w2v,
           float* __restrict__ pred, int nrows) {
    extern __shared__ char smem[];
    const uint32_t sb = smem_u32(smem);
    const int tid = threadIdx.x, lane = tid & 31, wid = tid >> 5;
    const int row0 = blockIdx.x * 64;
    const int g = lane >> 2, tig = lane & 3;
    const int m0 = (wid >> 1) * 16;
    const int nwn = (wid & 1) * 32;
    const int a_ro = (lane & 7) + ((lane >> 3) & 1) * 8;
    const int a_co = ((lane >> 4) & 1) * 8;
    const int b_ro = (lane & 7) + ((lane >> 4) & 1) * 8;
    const int b_co = ((lane >> 3) & 1) * 8;

    float* b1s = (float*)(smem + SM_B1);
    float* b2s = (float*)(smem + SM_B2);
    float* b1p = (float*)(smem + SM_B1P);
    float* w2s = (float*)(smem + SM_W2V);
    int*   s_ia = (int*)(smem + SM_IA);
    int*   s_ib = (int*)(smem + SM_IB);

    copyw_half(sb, tid, 10, 0);

    if (tid < 128) {
        b1s[tid] = en_b1[tid];
        b2s[tid] = en_b2[tid];
        b1p[tid] = pe_b1v[tid];
        w2s[tid] = pe_w2v[tid];
    }
    if (tid < 64) {
        int grow = row0 + tid;
        int ia = 0, ib = 0;
        if (grow < nrows) { ia = ip0[grow]; ib = ip1[grow]; }
        s_ia[tid] = ia; s_ib[tid] = ib;
        const char* qa = (const char*)(Qa + (size_t)ia * DD);
        const char* qb = (const char*)(Qb + (size_t)ib * DD);
        const char* ra = (const char*)(Ra + (size_t)ia * DD);
        const char* rb = (const char*)(Rb + (size_t)ib * DD);
        #pragma unroll
        for (int l = 0; l < 4; ++l) {
            asm volatile("prefetch.global.L2 [%0];" :: "l"(qa + l * 128));
            asm volatile("prefetch.global.L2 [%0];" :: "l"(qb + l * 128));
            asm volatile("prefetch.global.L2 [%0];" :: "l"(ra + l * 128));
            asm volatile("prefetch.global.L2 [%0];" :: "l"(rb + l * 128));
        }
    }

    float acc[2][4][4];
    zacc2(acc);

    // ---- en layer 1: e @ enW1c + Qa[s] + Qb[e] (staged gather) ----
    stage_a<128>(smem, wid, lane, row0, e, nrows);
    layer_gemm_issued<8>(sb, tid, 10, m0, nwn, a_ro, a_co, b_ro, b_co, acc);
    __syncthreads();                 // B reads done
    stage_p(smem, Qa, Qb, s_ia, s_ib, wid, lane);
    __syncthreads();
    pre_add_s(smem, acc, m0, nwn, g, tig);
    __syncthreads();                 // P reads done before W copy

    // ---- en layer 2 ----
    copyw_half(sb, tid, 11, 0);
    acc_to_A(smem, acc, m0, nwn, g, tig, b1s, true);
    zacc2(acc);
    layer_gemm_issued<8>(sb, tid, 11, m0, nwn, a_ro, a_co, b_ro, b_co, acc);

    // residual e: coalesced stage into PST (B free post-GEMM), then fold
    __syncthreads();                 // B reads done
    stage_rows(smem, e, row0, wid, lane);
    __syncthreads();
    {
        const float* rst = (const float*)(smem + SM_PST);
        const int rl = m0 + g;
        #pragma unroll
        for (int half = 0; half < 2; ++half) {
            const float* rrow = rst + (rl + half * 8) * PSTR;
            #pragma unroll
            for (int p = 0; p < 2; ++p)
                #pragma unroll
                for (int na = 0; na < 4; ++na) {
                    int cc = p * 64 + nwn + na * 8 + 2 * tig;
                    float2 rv = *(const float2*)(rrow + cc);
                    acc[p][na][half * 2 + 0] += b2s[cc] + rv.x;
                    acc[p][na][half * 2 + 1] += b2s[cc + 1] + rv.y;
                }
        }
    }

    // ---- pe layer 1: e_new @ peW1c + Ra[s] + Rb[e] (staged gather) ----
    __syncthreads();                 // PST reads done before W copy
    copyw_half(sb, tid, 14, 0);
    acc_to_A(smem, acc, m0, nwn, g, tig, nullptr, false);
    zacc2(acc);
    layer_gemm_issued<8>(sb, tid, 14, m0, nwn, a_ro, a_co, b_ro, b_co, acc);
    __syncthreads();                 // B reads done
    stage_p(smem, Ra, Rb, s_ia, s_ib, wid, lane);
    __syncthreads();
    pre_add_s(smem, acc, m0, nwn, g, tig);

    // ---- pe layer 2: per-row dot ----
    float* hT = (float*)(smem + SM_AH);
    __syncthreads();                 // A/P reads done before overwrite
    {
        const int rl = m0 + g;
        #pragma unroll
        for (int p = 0; p < 2; ++p)
            #pragma unroll
            for (int na = 0; na < 4; ++na) {
                int cc = p * 64 + nwn + na * 8 + 2 * tig;
                hT[rl * 129 + cc]           = fmaxf(acc[p][na][0] + b1p[cc], 0.f);
                hT[rl * 129 + cc + 1]       = fmaxf(acc[p][na][1] + b1p[cc + 1], 0.f);
                hT[(rl + 8) * 129 + cc]     = fmaxf(acc[p][na][2] + b1p[cc], 0.f);
                hT[(rl + 8) * 129 + cc + 1] = fmaxf(acc[p][na][3] + b1p[cc + 1], 0.f);
            }
    }
    __syncthreads();
    if (tid < 64) {
        int grow = row0 + tid;
        float a = __ldg(&pe_b2v[0]);
        #pragma unroll 8
        for (int k = 0; k < 128; ++k) a += hT[tid * 129 + k] * w2s[k];
        if (grow < nrows) pred[grow] = a;
    }
}

// ---------------------------------------------------------------------------
extern "C" void kernel_launch(void* const* d_in, const int* in_sizes, int n_in,
                              void* d_out, int out_size) {
    const float* nodes = (const float*)d_in[0];
    const void*  eidx  = d_in[1];
    const float* ne_W1 = (const float*)d_in[2];
    const float* ne_b1 = (const float*)d_in[3];
    const float* ne_W2 = (const float*)d_in[4];
    const float* ne_b2 = (const float*)d_in[5];
    const float* ee_W1 = (const float*)d_in[6];
    const float* ee_b1 = (const float*)d_in[7];
    const float* ee_W2 = (const float*)d_in[8];
    const float* ee_b2 = (const float*)d_in[9];
    const float* nn_W1 = (const float*)d_in[10];
    const float* nn_b1 = (const float*)d_in[11];
    const float* nn_W2 = (const float*)d_in[12];
    const float* nn_b2 = (const float*)d_in[13];
    const float* en_W1 = (const float*)d_in[14];
    const float* en_b1 = (const float*)d_in[15];
    const float* en_W2 = (const float*)d_in[16];
    const float* en_b2 = (const float*)d_in[17];
    const float* pe_W1 = (const float*)d_in[18];
    const float* pe_b1 = (const float*)d_in[19];
    const float* pe_W2 = (const float*)d_in[20];
    const float* pe_b2 = (const float*)d_in[21];

    float *h, *h2, *m0, *m1, *e, *pa, *pb, *pc, *pd;
    int *st, *en_;
    __nv_bfloat16 *pwh, *pwl;
    cudaGetSymbolAddress((void**)&h,   g_h);
    cudaGetSymbolAddress((void**)&h2,  g_h2);
    cudaGetSymbolAddress((void**)&m0,  g_m0);
    cudaGetSymbolAddress((void**)&m1,  g_m1);
    cudaGetSymbolAddress((void**)&e,   g_e);
    cudaGetSymbolAddress((void**)&pa,  g_pa);
    cudaGetSymbolAddress((void**)&pb,  g_pb);
    cudaGetSymbolAddress((void**)&pc,  g_pc);
    cudaGetSymbolAddress((void**)&pd,  g_pd);
    cudaGetSymbolAddress((void**)&st,  g_start);
    cudaGetSymbolAddress((void**)&en_, g_end);
    cudaGetSymbolAddress((void**)&pwh, g_pwh);
    cudaGetSymbolAddress((void**)&pwl, g_pwl);

    cudaFuncSetAttribute(node_fused<1, 1, false, true, false>,
                         cudaFuncAttributeMaxDynamicSharedMemorySize, SM_TOTAL);
    cudaFuncSetAttribute(node_fused<2, 8, true, false, true>,
                         cudaFuncAttributeMaxDynamicSharedMemorySize, SM_TOTAL);
    cudaFuncSetAttribute(node_fused<2, 8, true, true, true>,
                         cudaFuncAttributeMaxDynamicSharedMemorySize, SM_TOTAL);
    cudaFuncSetAttribute(edge_mlp<0, true, false>,
                         cudaFuncAttributeMaxDynamicSharedMemorySize, SM_TOTAL);
    cudaFuncSetAttribute(edge_mlp<1, true, true>,
                         cudaFuncAttributeMaxDynamicSharedMemorySize, SM_TOTAL);
    cudaFuncSetAttribute(edge_en_pe,
                         cudaFuncAttributeMaxDynamicSharedMemorySize, SM_TOTAL);

    const int nblk_n = (N_NODES + 63) / 64;  // 1563
    const int nblk_e = (N_EDGES + 63) / 64;  // 9375

    convert_idx_kernel<<<(2 * N_EDGES + 255) / 256, 256>>>(eidx, st, en_, N_EDGES);
    pack_w_kernel<<<(15 * 16384 + 255) / 256, 256>>>(
        ne_W1, ne_W2, ee_W1, ee_W2, nn_W1, nn_W2, en_W1, en_W2, pe_W1, pwh, pwl);

    // h = MLP_ne(nodes);  Pa = h@eeW1a, Pb = h@eeW1b;  zero m0
    node_fused<1, 1, false, true, false><<<nblk_n, 256, SM_TOTAL>>>(
        nodes, nullptr, 0, 0, nullptr, nullptr, 0, 1,
        2, 3, pa, pb, ne_b1, ne_b2, nullptr, h, m0, N_NODES);

    // e = relu(Pa[s]+Pb[e]+b1)@eeW2 + b2;  scatter e -> m0
    edge_mlp<0, true, false><<<nblk_e, 256, SM_TOTAL>>>(
        nullptr, st, en_, pa, pb, 0, 4,
        ee_b1, ee_b2, nullptr, e, m0, N_EDGES);

    float* hA = h;
    float* hB = h2;
    float* msgs[2] = {m0, m1};

    for (int it = 0; it < NUM_ITERS; ++it) {
        float* mcur = msgs[it & 1];
        float* mnxt = msgs[(it + 1) & 1];
        const bool last = (it == NUM_ITERS - 1);
        float* zr = last ? nullptr : mnxt;

        if (!last) {
            node_fused<2, 8, true, false, true><<<nblk_n, 256, SM_TOTAL>>>(
                hA, mcur, 8, 9, pa, pb, 5, 7,
                0, 0, nullptr, nullptr, nn_b1, nn_b2, hA, hB, zr, N_NODES);

            edge_mlp<1, true, true><<<nblk_e, 256, SM_TOTAL>>>(
                e, st, en_, pa, pb, 10, 11,
                en_b1, en_b2, e, e, mnxt, N_EDGES);
        } else {
            node_fused<2, 8, true, true, true><<<nblk_n, 256, SM_TOTAL>>>(
                hA, mcur, 8, 9, pa, pb, 5, 7,
                12, 13, pc, pd, nn_b1, nn_b2, hA, hB, zr, N_NODES);

            edge_en_pe<<<nblk_e, 256, SM_TOTAL>>>(
                e, st, en_, pa, pb, pc, pd,
                en_b1, en_b2, pe_b1, pe_b2, pe_W2,
                (float*)d_out, N_EDGES);
        }

        float* t = hA; hA = hB; hB = t;
    }
}